// round 1
// baseline (speedup 1.0000x reference)
#include <cuda_runtime.h>
#include <math.h>

#define BATCH 64
#define CH    128
#define LEN   1024
#define ROWS  (BATCH*CH)          /* 8192  */
#define FEAT  (CH*LEN)            /* 131072 */
#define NELEM (BATCH*CH*LEN)      /* 8388608 */

/* ---------------- scratch (static device globals; allocation-free) -------- */
__device__ float g_xn[NELEM];                /* normalized x; also up_1 / down_1 */
__device__ float g_trend1[NELEM];            /* trend for s=1                     */
__device__ float g_dstack[2 * ROWS * 512];   /* [down ; trend_ds] stacked, max Ls */
__device__ float g_h[2 * ROWS * LEN];        /* GEMM1 output (gelu'd)             */
__device__ float g_out8[2 * ROWS * LEN];     /* rows 0..8191: up, 8192..: trend   */
__device__ float g_out4[2 * ROWS * LEN];
__device__ float g_out2[2 * ROWS * LEN];
__device__ float g_means[4 * 2 * ROWS];      /* [scaleIdx][up/trend][row]         */
__device__ float g_gates[BATCH * 4];

/* ---------------- BatchNorm over batch axis ------------------------------- */
__global__ void bn_kernel(const float* __restrict__ x,
                          const float* __restrict__ gam,
                          const float* __restrict__ bet) {
    int f = blockIdx.x * blockDim.x + threadIdx.x;
    if (f >= FEAT) return;
    float v[BATCH];
    float s = 0.f;
#pragma unroll
    for (int b = 0; b < BATCH; b++) { v[b] = x[(size_t)b * FEAT + f]; s += v[b]; }
    float mu = s * (1.f / BATCH);
    float q = 0.f;
#pragma unroll
    for (int b = 0; b < BATCH; b++) { float d = v[b] - mu; q += d * d; }
    float inv = rsqrtf(q * (1.f / BATCH) + 1e-5f);
    float gg = gam[f] * inv, bb = bet[f];
#pragma unroll
    for (int b = 0; b < BATCH; b++)
        g_xn[(size_t)b * FEAT + f] = (v[b] - mu) * gg + bb;
}

/* ---------------- depthwise strided conv ---------------------------------- */
__global__ void dwconv_kernel(const float* __restrict__ xn,
                              const float* __restrict__ cw,
                              float* __restrict__ out, int s, int Ls) {
    int idx = blockIdx.x * blockDim.x + threadIdx.x;
    if (idx >= ROWS * Ls) return;
    int t = idx % Ls, row = idx / Ls, c = row % CH;
    const float* xr = xn + (size_t)row * LEN;
    const float* w  = cw + c * 2 * s;
    int base = t * s - s / 2;
    float acc = 0.f;
    for (int k = 0; k < 2 * s; k++) {
        int p = base + k;
        if (p >= 0 && p < LEN) acc = fmaf(xr[p], w[k], acc);
    }
    out[idx] = acc;
}

/* ---------------- EMA: exact reference formulation (cumsum of weighted x) - */
__global__ void ema_kernel(const float* __restrict__ src,
                           float* __restrict__ dst,
                           const float* __restrict__ al, int Ls) {
    int warp = (blockIdx.x * blockDim.x + threadIdx.x) >> 5;
    int lane = threadIdx.x & 31;
    if (warp >= ROWS) return;
    int c = warp % CH;
    float a  = 1.f / (1.f + expf(-al[c]));
    float om = 1.f - a;
    float l2 = log2f(om);
    const float* x = src + (size_t)warp * Ls;
    float* y       = dst + (size_t)warp * Ls;
    float cnum = 0.f, cden = 0.f;
    for (int j0 = 0; j0 < Ls; j0 += 32) {
        int j = j0 + lane;
        float p = (float)(Ls - 1 - j);
        float base = exp2f(p * l2);              /* (1-a)^(Ls-1-j), underflows like ref */
        float wn = (j == 0) ? base : base * a;
        float n = x[j] * wn;
        float d = base;
#pragma unroll
        for (int o = 1; o < 32; o <<= 1) {
            float nn = __shfl_up_sync(0xffffffffu, n, o);
            float dd = __shfl_up_sync(0xffffffffu, d, o);
            if (lane >= o) { n += nn; d += dd; }
        }
        n += cnum; d += cden;
        y[j] = n / fmaxf(d, 1e-12f);
        cnum = __shfl_sync(0xffffffffu, n, 31);
        cden = __shfl_sync(0xffffffffu, d, 31);
    }
}

/* ---------------- fp32 tiled GEMM:  C[M,N] = A[M,K] * B[N,K]^T  (NT) ------ */
/* BM=BN=128, BK=16, 256 threads, 8x8 per thread. Optional exact-gelu+bias.   */
__global__ void __launch_bounds__(256)
gemm_nt_kernel(const float* __restrict__ A, const float* __restrict__ B,
               float* __restrict__ C, const float* __restrict__ bias,
               int K, int act) {
    __shared__ float As[16][132];
    __shared__ float Bs[16][132];
    const int N = 1024;
    int tid = threadIdx.x;
    int m0 = blockIdx.y * 128, n0 = blockIdx.x * 128;
    int tm0 = (tid >> 4) * 8, tn0 = (tid & 15) * 8;
    float acc[8][8];
#pragma unroll
    for (int i = 0; i < 8; i++)
#pragma unroll
        for (int j = 0; j < 8; j++) acc[i][j] = 0.f;

    for (int k0 = 0; k0 < K; k0 += 16) {
#pragma unroll
        for (int it = 0; it < 2; it++) {
            int slot = tid * 2 + it;             /* 0..511 */
            int row = slot >> 2, kq = (slot & 3) << 2;
            float4 va = *(const float4*)(A + (size_t)(m0 + row) * K + k0 + kq);
            As[kq + 0][row] = va.x; As[kq + 1][row] = va.y;
            As[kq + 2][row] = va.z; As[kq + 3][row] = va.w;
            float4 vb = *(const float4*)(B + (size_t)(n0 + row) * K + k0 + kq);
            Bs[kq + 0][row] = vb.x; Bs[kq + 1][row] = vb.y;
            Bs[kq + 2][row] = vb.z; Bs[kq + 3][row] = vb.w;
        }
        __syncthreads();
#pragma unroll
        for (int k = 0; k < 16; k++) {
            float ra[8], rb[8];
#pragma unroll
            for (int i = 0; i < 8; i++) ra[i] = As[k][tm0 + i];
#pragma unroll
            for (int j = 0; j < 8; j++) rb[j] = Bs[k][tn0 + j];
#pragma unroll
            for (int i = 0; i < 8; i++)
#pragma unroll
                for (int j = 0; j < 8; j++)
                    acc[i][j] = fmaf(ra[i], rb[j], acc[i][j]);
        }
        __syncthreads();
    }
#pragma unroll
    for (int i = 0; i < 8; i++) {
#pragma unroll
        for (int j = 0; j < 8; j++) {
            int n = n0 + tn0 + j;
            float v = acc[i][j] + bias[n];
            if (act) v = 0.5f * v * (1.f + erff(v * 0.70710678118654752f));
            C[(size_t)(m0 + tm0 + i) * N + n] = v;
        }
    }
}

/* ---------------- per-row mean over L -------------------------------------- */
__global__ void rowmean_kernel(const float* __restrict__ src,
                               float* __restrict__ dst) {
    int row = blockIdx.x;
    const float* p = src + (size_t)row * LEN;
    float s = 0.f;
    for (int i = threadIdx.x; i < LEN; i += 256) s += p[i];
    __shared__ float sm[256];
    sm[threadIdx.x] = s; __syncthreads();
    for (int o = 128; o > 0; o >>= 1) {
        if (threadIdx.x < o) sm[threadIdx.x] += sm[threadIdx.x + o];
        __syncthreads();
    }
    if (threadIdx.x == 0) dst[row] = sm[0] * (1.f / LEN);
}

/* ---------------- gates ----------------------------------------------------- */
__global__ void gate_kernel(const float* __restrict__ gw8, const float* __restrict__ gb8,
                            const float* __restrict__ gw4, const float* __restrict__ gb4,
                            const float* __restrict__ gw2, const float* __restrict__ gb2,
                            const float* __restrict__ gw1, const float* __restrict__ gb1) {
    int b = blockIdx.x;
    int c = threadIdx.x;                 /* 128 threads */
    __shared__ float red[4][128];
    const float* gws[4] = {gw8, gw4, gw2, gw1};
    for (int s = 0; s < 4; s++) {
        float um = g_means[(s * 2 + 0) * ROWS + b * CH + c];
        float tm = g_means[(s * 2 + 1) * ROWS + b * CH + c];
        red[s][c] = (um - tm) * gws[s][c];
    }
    __syncthreads();
    for (int o = 64; o > 0; o >>= 1) {
        if (c < o) {
            for (int s = 0; s < 4; s++) red[s][c] += red[s][c + o];
        }
        __syncthreads();
    }
    if (c == 0) {
        float gbv[4] = {gb8[0], gb4[0], gb2[0], gb1[0]};
        float gv[4], tot = 0.f;
        for (int s = 0; s < 4; s++) {
            gv[s] = 1.f / (1.f + expf(-(red[s][0] + gbv[s])));
            tot += gv[s];
        }
        for (int s = 0; s < 4; s++) g_gates[b * 4 + s] = gv[s] / (tot + 1e-6f);
    }
}

/* ---------------- final weighted combine; out = [season ; trend] ----------- */
__global__ void combine_kernel(float* __restrict__ out) {
    size_t idx = blockIdx.x * (size_t)blockDim.x + threadIdx.x;
    if (idx >= NELEM) return;
    int b = (int)(idx >> 10) / CH;
    const float* G = g_gates + b * 4;
    float g0 = G[0], g1 = G[1], g2 = G[2], g3 = G[3];
    float u8 = g_out8[idx], t8 = g_out8[idx + (size_t)NELEM];
    float u4 = g_out4[idx], t4 = g_out4[idx + (size_t)NELEM];
    float u2 = g_out2[idx], t2 = g_out2[idx + (size_t)NELEM];
    float u1 = g_xn[idx],   t1 = g_trend1[idx];
    float trend  = g0 * t8 + g1 * t4 + g2 * t2 + g3 * t1;
    float season = g0 * (u8 - t8) + g1 * (u4 - t4) + g2 * (u2 - t2) + g3 * (u1 - t1);
    out[idx] = season;
    out[(size_t)NELEM + idx] = trend;
}

/* ---------------- host orchestration -------------------------------------- */
extern "C" void kernel_launch(void* const* d_in, const int* in_sizes, int n_in,
                              void* d_out, int out_size) {
    const float* x    = (const float*)d_in[0];
    const float* bng  = (const float*)d_in[1];
    const float* bnb  = (const float*)d_in[2];
    const float* cw8  = (const float*)d_in[3];
    const float* w1_8 = (const float*)d_in[4];
    const float* b1_8 = (const float*)d_in[5];
    const float* w2_8 = (const float*)d_in[6];
    const float* b2_8 = (const float*)d_in[7];
    const float* cw4  = (const float*)d_in[8];
    const float* w1_4 = (const float*)d_in[9];
    const float* b1_4 = (const float*)d_in[10];
    const float* w2_4 = (const float*)d_in[11];
    const float* b2_4 = (const float*)d_in[12];
    const float* cw2  = (const float*)d_in[13];
    const float* w1_2 = (const float*)d_in[14];
    const float* b1_2 = (const float*)d_in[15];
    const float* w2_2 = (const float*)d_in[16];
    const float* b2_2 = (const float*)d_in[17];
    const float* gw8  = (const float*)d_in[18];
    const float* gb8  = (const float*)d_in[19];
    const float* al8  = (const float*)d_in[20];
    const float* gw4  = (const float*)d_in[21];
    const float* gb4  = (const float*)d_in[22];
    const float* al4  = (const float*)d_in[23];
    const float* gw2  = (const float*)d_in[24];
    const float* gb2  = (const float*)d_in[25];
    const float* al2  = (const float*)d_in[26];
    const float* gw1  = (const float*)d_in[27];
    const float* gb1  = (const float*)d_in[28];
    const float* al1  = (const float*)d_in[29];
    float* out = (float*)d_out;

    float *xn, *tr1, *dst, *h, *o8, *o4, *o2, *means;
    cudaGetSymbolAddress((void**)&xn,    g_xn);
    cudaGetSymbolAddress((void**)&tr1,   g_trend1);
    cudaGetSymbolAddress((void**)&dst,   g_dstack);
    cudaGetSymbolAddress((void**)&h,     g_h);
    cudaGetSymbolAddress((void**)&o8,    g_out8);
    cudaGetSymbolAddress((void**)&o4,    g_out4);
    cudaGetSymbolAddress((void**)&o2,    g_out2);
    cudaGetSymbolAddress((void**)&means, g_means);

    /* BatchNorm */
    bn_kernel<<<FEAT / 256, 256>>>(x, bng, bnb);

    /* s = 1 branch: trend1 = EMA(xn) */
    ema_kernel<<<ROWS / 8, 256>>>(xn, tr1, al1, LEN);

    /* s = 8 */
    {
        const int Ls = 128;
        dwconv_kernel<<<(ROWS * Ls + 255) / 256, 256>>>(xn, cw8, dst, 8, Ls);
        ema_kernel<<<ROWS / 8, 256>>>(dst, dst + (size_t)ROWS * Ls, al8, Ls);
        gemm_nt_kernel<<<dim3(8, 128), 256>>>(dst, w1_8, h, b1_8, Ls, 1);
        gemm_nt_kernel<<<dim3(8, 128), 256>>>(h, w2_8, o8, b2_8, 1024, 0);
    }
    /* s = 4 */
    {
        const int Ls = 256;
        dwconv_kernel<<<(ROWS * Ls + 255) / 256, 256>>>(xn, cw4, dst, 4, Ls);
        ema_kernel<<<ROWS / 8, 256>>>(dst, dst + (size_t)ROWS * Ls, al4, Ls);
        gemm_nt_kernel<<<dim3(8, 128), 256>>>(dst, w1_4, h, b1_4, Ls, 1);
        gemm_nt_kernel<<<dim3(8, 128), 256>>>(h, w2_4, o4, b2_4, 1024, 0);
    }
    /* s = 2 */
    {
        const int Ls = 512;
        dwconv_kernel<<<(ROWS * Ls + 255) / 256, 256>>>(xn, cw2, dst, 2, Ls);
        ema_kernel<<<ROWS / 8, 256>>>(dst, dst + (size_t)ROWS * Ls, al2, Ls);
        gemm_nt_kernel<<<dim3(8, 128), 256>>>(dst, w1_2, h, b1_2, Ls, 1);
        gemm_nt_kernel<<<dim3(8, 128), 256>>>(h, w2_2, o2, b2_2, 1024, 0);
    }

    /* per-row means (up & trend) for gating */
    rowmean_kernel<<<2 * ROWS, 256>>>(o8, means + 0 * 2 * ROWS);
    rowmean_kernel<<<2 * ROWS, 256>>>(o4, means + 1 * 2 * ROWS);
    rowmean_kernel<<<2 * ROWS, 256>>>(o2, means + 2 * 2 * ROWS);
    rowmean_kernel<<<ROWS, 256>>>(xn,  means + 3 * 2 * ROWS);
    rowmean_kernel<<<ROWS, 256>>>(tr1, means + 3 * 2 * ROWS + ROWS);

    gate_kernel<<<BATCH, 128>>>(gw8, gb8, gw4, gb4, gw2, gb2, gw1, gb1);

    combine_kernel<<<(NELEM + 255) / 256, 256>>>(out);
}

// round 2
// speedup vs baseline: 2.0918x; 2.0918x over previous
#include <cuda_runtime.h>
#include <math.h>
#include <stdint.h>

#define BATCH 64
#define CH    128
#define LEN   1024
#define ROWS  (BATCH*CH)          /* 8192  */
#define FEAT  (CH*LEN)            /* 131072 */
#define NELEM (BATCH*CH*LEN)      /* 8388608 */

/* ---------------- scratch (static device globals; allocation-free) -------- */
__device__ float g_xn[NELEM];                /* normalized x; also up_1 / down_1 */
__device__ float g_trend1[NELEM];            /* trend for s=1                     */
__device__ float g_dstack[2 * ROWS * 512];   /* [down ; trend_ds] stacked, max Ls */
__device__ float g_h[2 * ROWS * LEN];        /* GEMM1 output (gelu'd)             */
__device__ float g_out8[2 * ROWS * LEN];     /* rows 0..8191: up, 8192..: trend   */
__device__ float g_out4[2 * ROWS * LEN];
__device__ float g_out2[2 * ROWS * LEN];
__device__ float g_means[4 * 2 * ROWS];      /* [scaleIdx][up/trend][row]         */
__device__ float g_gates[BATCH * 4];

/* ---------------- BatchNorm over batch axis ------------------------------- */
__global__ void bn_kernel(const float* __restrict__ x,
                          const float* __restrict__ gam,
                          const float* __restrict__ bet) {
    int f = blockIdx.x * blockDim.x + threadIdx.x;
    if (f >= FEAT) return;
    float v[BATCH];
    float s = 0.f;
#pragma unroll
    for (int b = 0; b < BATCH; b++) { v[b] = x[(size_t)b * FEAT + f]; s += v[b]; }
    float mu = s * (1.f / BATCH);
    float q = 0.f;
#pragma unroll
    for (int b = 0; b < BATCH; b++) { float d = v[b] - mu; q += d * d; }
    float inv = rsqrtf(q * (1.f / BATCH) + 1e-5f);
    float gg = gam[f] * inv, bb = bet[f];
#pragma unroll
    for (int b = 0; b < BATCH; b++)
        g_xn[(size_t)b * FEAT + f] = (v[b] - mu) * gg + bb;
}

/* ---------------- depthwise strided conv ---------------------------------- */
__global__ void dwconv_kernel(const float* __restrict__ xn,
                              const float* __restrict__ cw,
                              float* __restrict__ out, int s, int Ls) {
    int idx = blockIdx.x * blockDim.x + threadIdx.x;
    if (idx >= ROWS * Ls) return;
    int t = idx % Ls, row = idx / Ls, c = row % CH;
    const float* xr = xn + (size_t)row * LEN;
    const float* w  = cw + c * 2 * s;
    int base = t * s - s / 2;
    float acc = 0.f;
    for (int k = 0; k < 2 * s; k++) {
        int p = base + k;
        if (p >= 0 && p < LEN) acc = fmaf(xr[p], w[k], acc);
    }
    out[idx] = acc;
}

/* ---------------- EMA: exact reference formulation (cumsum of weighted x) - */
__global__ void ema_kernel(const float* __restrict__ src,
                           float* __restrict__ dst,
                           const float* __restrict__ al, int Ls) {
    int warp = (blockIdx.x * blockDim.x + threadIdx.x) >> 5;
    int lane = threadIdx.x & 31;
    if (warp >= ROWS) return;
    int c = warp % CH;
    float a  = 1.f / (1.f + expf(-al[c]));
    float om = 1.f - a;
    float l2 = log2f(om);
    const float* x = src + (size_t)warp * Ls;
    float* y       = dst + (size_t)warp * Ls;
    float cnum = 0.f, cden = 0.f;
    for (int j0 = 0; j0 < Ls; j0 += 32) {
        int j = j0 + lane;
        float p = (float)(Ls - 1 - j);
        float base = exp2f(p * l2);              /* (1-a)^(Ls-1-j), underflows like ref */
        float wn = (j == 0) ? base : base * a;
        float n = x[j] * wn;
        float d = base;
#pragma unroll
        for (int o = 1; o < 32; o <<= 1) {
            float nn = __shfl_up_sync(0xffffffffu, n, o);
            float dd = __shfl_up_sync(0xffffffffu, d, o);
            if (lane >= o) { n += nn; d += dd; }
        }
        n += cnum; d += cden;
        y[j] = n / fmaxf(d, 1e-12f);
        cnum = __shfl_sync(0xffffffffu, n, 31);
        cden = __shfl_sync(0xffffffffu, d, 31);
    }
}

/* ---------------- TF32 tensor-core GEMM:  C[M,N] = A[M,K] * B[N,K]^T ------ */
/* BM=BN=128, BK=16, 256 threads = 8 warps (4x2), warp tile 32x64.            */
/* smem [k][m] pitch 136 -> conflict-free m16n8k8 fragment loads.             */

__device__ __forceinline__ uint32_t f2tf32(float x) {
    uint32_t r;
    asm("cvt.rna.tf32.f32 %0, %1;" : "=r"(r) : "f"(x));
    return r;
}

__device__ __forceinline__ void mma_tf32(float* d,
                                         const uint32_t* a, const uint32_t* b,
                                         const float* c) {
    asm volatile(
        "mma.sync.aligned.m16n8k8.row.col.f32.tf32.tf32.f32 "
        "{%0,%1,%2,%3}, {%4,%5,%6,%7}, {%8,%9}, {%10,%11,%12,%13};"
        : "=f"(d[0]), "=f"(d[1]), "=f"(d[2]), "=f"(d[3])
        : "r"(a[0]), "r"(a[1]), "r"(a[2]), "r"(a[3]),
          "r"(b[0]), "r"(b[1]),
          "f"(c[0]), "f"(c[1]), "f"(c[2]), "f"(c[3]));
}

#define SPITCH 136

__global__ void __launch_bounds__(256, 2)
gemm_tc_kernel(const float* __restrict__ A, const float* __restrict__ B,
               float* __restrict__ C, const float* __restrict__ bias,
               int K, int act) {
    __shared__ uint32_t As[16][SPITCH];
    __shared__ uint32_t Bs[16][SPITCH];
    const int N = 1024;
    const int tid  = threadIdx.x;
    const int wid  = tid >> 5;
    const int lane = tid & 31;
    const int g    = lane >> 2;          /* groupID          */
    const int tg   = lane & 3;           /* thread-in-group  */
    const int wm   = (wid >> 1) * 32;    /* warp m offset    */
    const int wn   = (wid & 1) * 64;     /* warp n offset    */
    const int m0 = blockIdx.y * 128, n0 = blockIdx.x * 128;

    /* loader mapping: slot = tid*2+it -> row = slot>>2, kq = (slot&3)*4 */
    const int lrow = tid >> 1;
    const int lkq  = (tid & 1) * 8;

    float acc[2][8][4];
#pragma unroll
    for (int i = 0; i < 2; i++)
#pragma unroll
        for (int j = 0; j < 8; j++)
#pragma unroll
            for (int q = 0; q < 4; q++) acc[i][j][q] = 0.f;

    float4 pa[2], pb[2];
#pragma unroll
    for (int it = 0; it < 2; it++) {
        pa[it] = *(const float4*)(A + (size_t)(m0 + lrow) * K + lkq + it * 4);
        pb[it] = *(const float4*)(B + (size_t)(n0 + lrow) * K + lkq + it * 4);
    }

    for (int k0 = 0; k0 < K; k0 += 16) {
#pragma unroll
        for (int it = 0; it < 2; it++) {
            int kq = lkq + it * 4;
            As[kq + 0][lrow] = f2tf32(pa[it].x);
            As[kq + 1][lrow] = f2tf32(pa[it].y);
            As[kq + 2][lrow] = f2tf32(pa[it].z);
            As[kq + 3][lrow] = f2tf32(pa[it].w);
            Bs[kq + 0][lrow] = f2tf32(pb[it].x);
            Bs[kq + 1][lrow] = f2tf32(pb[it].y);
            Bs[kq + 2][lrow] = f2tf32(pb[it].z);
            Bs[kq + 3][lrow] = f2tf32(pb[it].w);
        }
        __syncthreads();

        if (k0 + 16 < K) {
#pragma unroll
            for (int it = 0; it < 2; it++) {
                pa[it] = *(const float4*)(A + (size_t)(m0 + lrow) * K + k0 + 16 + lkq + it * 4);
                pb[it] = *(const float4*)(B + (size_t)(n0 + lrow) * K + k0 + 16 + lkq + it * 4);
            }
        }

#pragma unroll
        for (int kk = 0; kk < 16; kk += 8) {
            uint32_t af[2][4], bf[8][2];
#pragma unroll
            for (int mt = 0; mt < 2; mt++) {
                int m = wm + mt * 16;
                af[mt][0] = As[kk + tg    ][m + g    ];
                af[mt][1] = As[kk + tg    ][m + g + 8];
                af[mt][2] = As[kk + tg + 4][m + g    ];
                af[mt][3] = As[kk + tg + 4][m + g + 8];
            }
#pragma unroll
            for (int nt = 0; nt < 8; nt++) {
                int n = wn + nt * 8;
                bf[nt][0] = Bs[kk + tg    ][n + g];
                bf[nt][1] = Bs[kk + tg + 4][n + g];
            }
#pragma unroll
            for (int mt = 0; mt < 2; mt++)
#pragma unroll
                for (int nt = 0; nt < 8; nt++)
                    mma_tf32(acc[mt][nt], af[mt], bf[nt], acc[mt][nt]);
        }
        __syncthreads();
    }

    /* epilogue: bias (+ exact gelu) */
#pragma unroll
    for (int mt = 0; mt < 2; mt++) {
        int r0 = m0 + wm + mt * 16 + g;
#pragma unroll
        for (int nt = 0; nt < 8; nt++) {
            int c0 = n0 + wn + nt * 8 + 2 * tg;
            float b0 = bias[c0], b1 = bias[c0 + 1];
            float v0 = acc[mt][nt][0] + b0;
            float v1 = acc[mt][nt][1] + b1;
            float v2 = acc[mt][nt][2] + b0;
            float v3 = acc[mt][nt][3] + b1;
            if (act) {
                v0 = 0.5f * v0 * (1.f + erff(v0 * 0.70710678118654752f));
                v1 = 0.5f * v1 * (1.f + erff(v1 * 0.70710678118654752f));
                v2 = 0.5f * v2 * (1.f + erff(v2 * 0.70710678118654752f));
                v3 = 0.5f * v3 * (1.f + erff(v3 * 0.70710678118654752f));
            }
            *(float2*)(C + (size_t)r0 * N + c0)       = make_float2(v0, v1);
            *(float2*)(C + (size_t)(r0 + 8) * N + c0) = make_float2(v2, v3);
        }
    }
}

/* ---------------- per-row mean over L -------------------------------------- */
__global__ void rowmean_kernel(const float* __restrict__ src,
                               float* __restrict__ dst) {
    int row = blockIdx.x;
    const float* p = src + (size_t)row * LEN;
    float s = 0.f;
    for (int i = threadIdx.x; i < LEN; i += 256) s += p[i];
    __shared__ float sm[256];
    sm[threadIdx.x] = s; __syncthreads();
    for (int o = 128; o > 0; o >>= 1) {
        if (threadIdx.x < o) sm[threadIdx.x] += sm[threadIdx.x + o];
        __syncthreads();
    }
    if (threadIdx.x == 0) dst[row] = sm[0] * (1.f / LEN);
}

/* ---------------- gates ----------------------------------------------------- */
__global__ void gate_kernel(const float* __restrict__ gw8, const float* __restrict__ gb8,
                            const float* __restrict__ gw4, const float* __restrict__ gb4,
                            const float* __restrict__ gw2, const float* __restrict__ gb2,
                            const float* __restrict__ gw1, const float* __restrict__ gb1) {
    int b = blockIdx.x;
    int c = threadIdx.x;                 /* 128 threads */
    __shared__ float red[4][128];
    const float* gws[4] = {gw8, gw4, gw2, gw1};
    for (int s = 0; s < 4; s++) {
        float um = g_means[(s * 2 + 0) * ROWS + b * CH + c];
        float tm = g_means[(s * 2 + 1) * ROWS + b * CH + c];
        red[s][c] = (um - tm) * gws[s][c];
    }
    __syncthreads();
    for (int o = 64; o > 0; o >>= 1) {
        if (c < o) {
            for (int s = 0; s < 4; s++) red[s][c] += red[s][c + o];
        }
        __syncthreads();
    }
    if (c == 0) {
        float gbv[4] = {gb8[0], gb4[0], gb2[0], gb1[0]};
        float gv[4], tot = 0.f;
        for (int s = 0; s < 4; s++) {
            gv[s] = 1.f / (1.f + expf(-(red[s][0] + gbv[s])));
            tot += gv[s];
        }
        for (int s = 0; s < 4; s++) g_gates[b * 4 + s] = gv[s] / (tot + 1e-6f);
    }
}

/* ---------------- final weighted combine; out = [season ; trend] ----------- */
__global__ void combine_kernel(float* __restrict__ out) {
    size_t idx = blockIdx.x * (size_t)blockDim.x + threadIdx.x;
    if (idx >= NELEM) return;
    int b = (int)(idx >> 10) / CH;
    const float* G = g_gates + b * 4;
    float g0 = G[0], g1 = G[1], g2 = G[2], g3 = G[3];
    float u8 = g_out8[idx], t8 = g_out8[idx + (size_t)NELEM];
    float u4 = g_out4[idx], t4 = g_out4[idx + (size_t)NELEM];
    float u2 = g_out2[idx], t2 = g_out2[idx + (size_t)NELEM];
    float u1 = g_xn[idx],   t1 = g_trend1[idx];
    float trend  = g0 * t8 + g1 * t4 + g2 * t2 + g3 * t1;
    float season = g0 * (u8 - t8) + g1 * (u4 - t4) + g2 * (u2 - t2) + g3 * (u1 - t1);
    out[idx] = season;
    out[(size_t)NELEM + idx] = trend;
}

/* ---------------- host orchestration -------------------------------------- */
extern "C" void kernel_launch(void* const* d_in, const int* in_sizes, int n_in,
                              void* d_out, int out_size) {
    const float* x    = (const float*)d_in[0];
    const float* bng  = (const float*)d_in[1];
    const float* bnb  = (const float*)d_in[2];
    const float* cw8  = (const float*)d_in[3];
    const float* w1_8 = (const float*)d_in[4];
    const float* b1_8 = (const float*)d_in[5];
    const float* w2_8 = (const float*)d_in[6];
    const float* b2_8 = (const float*)d_in[7];
    const float* cw4  = (const float*)d_in[8];
    const float* w1_4 = (const float*)d_in[9];
    const float* b1_4 = (const float*)d_in[10];
    const float* w2_4 = (const float*)d_in[11];
    const float* b2_4 = (const float*)d_in[12];
    const float* cw2  = (const float*)d_in[13];
    const float* w1_2 = (const float*)d_in[14];
    const float* b1_2 = (const float*)d_in[15];
    const float* w2_2 = (const float*)d_in[16];
    const float* b2_2 = (const float*)d_in[17];
    const float* gw8  = (const float*)d_in[18];
    const float* gb8  = (const float*)d_in[19];
    const float* al8  = (const float*)d_in[20];
    const float* gw4  = (const float*)d_in[21];
    const float* gb4  = (const float*)d_in[22];
    const float* al4  = (const float*)d_in[23];
    const float* gw2  = (const float*)d_in[24];
    const float* gb2  = (const float*)d_in[25];
    const float* al2  = (const float*)d_in[26];
    const float* gw1  = (const float*)d_in[27];
    const float* gb1  = (const float*)d_in[28];
    const float* al1  = (const float*)d_in[29];
    float* out = (float*)d_out;

    float *xn, *tr1, *dst, *h, *o8, *o4, *o2, *means;
    cudaGetSymbolAddress((void**)&xn,    g_xn);
    cudaGetSymbolAddress((void**)&tr1,   g_trend1);
    cudaGetSymbolAddress((void**)&dst,   g_dstack);
    cudaGetSymbolAddress((void**)&h,     g_h);
    cudaGetSymbolAddress((void**)&o8,    g_out8);
    cudaGetSymbolAddress((void**)&o4,    g_out4);
    cudaGetSymbolAddress((void**)&o2,    g_out2);
    cudaGetSymbolAddress((void**)&means, g_means);

    /* BatchNorm */
    bn_kernel<<<FEAT / 256, 256>>>(x, bng, bnb);

    /* s = 1 branch: trend1 = EMA(xn) */
    ema_kernel<<<ROWS / 8, 256>>>(xn, tr1, al1, LEN);

    /* s = 8 */
    {
        const int Ls = 128;
        dwconv_kernel<<<(ROWS * Ls + 255) / 256, 256>>>(xn, cw8, dst, 8, Ls);
        ema_kernel<<<ROWS / 8, 256>>>(dst, dst + (size_t)ROWS * Ls, al8, Ls);
        gemm_tc_kernel<<<dim3(8, 128), 256>>>(dst, w1_8, h, b1_8, Ls, 1);
        gemm_tc_kernel<<<dim3(8, 128), 256>>>(h, w2_8, o8, b2_8, 1024, 0);
    }
    /* s = 4 */
    {
        const int Ls = 256;
        dwconv_kernel<<<(ROWS * Ls + 255) / 256, 256>>>(xn, cw4, dst, 4, Ls);
        ema_kernel<<<ROWS / 8, 256>>>(dst, dst + (size_t)ROWS * Ls, al4, Ls);
        gemm_tc_kernel<<<dim3(8, 128), 256>>>(dst, w1_4, h, b1_4, Ls, 1);
        gemm_tc_kernel<<<dim3(8, 128), 256>>>(h, w2_4, o4, b2_4, 1024, 0);
    }
    /* s = 2 */
    {
        const int Ls = 512;
        dwconv_kernel<<<(ROWS * Ls + 255) / 256, 256>>>(xn, cw2, dst, 2, Ls);
        ema_kernel<<<ROWS / 8, 256>>>(dst, dst + (size_t)ROWS * Ls, al2, Ls);
        gemm_tc_kernel<<<dim3(8, 128), 256>>>(dst, w1_2, h, b1_2, Ls, 1);
        gemm_tc_kernel<<<dim3(8, 128), 256>>>(h, w2_2, o2, b2_2, 1024, 0);
    }

    /* per-row means (up & trend) for gating */
    rowmean_kernel<<<2 * ROWS, 256>>>(o8, means + 0 * 2 * ROWS);
    rowmean_kernel<<<2 * ROWS, 256>>>(o4, means + 1 * 2 * ROWS);
    rowmean_kernel<<<2 * ROWS, 256>>>(o2, means + 2 * 2 * ROWS);
    rowmean_kernel<<<ROWS, 256>>>(xn,  means + 3 * 2 * ROWS);
    rowmean_kernel<<<ROWS, 256>>>(tr1, means + 3 * 2 * ROWS + ROWS);

    gate_kernel<<<BATCH, 128>>>(gw8, gb8, gw4, gb4, gw2, gb2, gw1, gb1);

    combine_kernel<<<(NELEM + 255) / 256, 256>>>(out);
}

// round 3
// speedup vs baseline: 2.4787x; 1.1849x over previous
#include <cuda_runtime.h>
#include <math.h>
#include <stdint.h>

#define BATCH 64
#define CH    128
#define LEN   1024
#define ROWS  (BATCH*CH)          /* 8192  */
#define FEAT  (CH*LEN)            /* 131072 */
#define NELEM (BATCH*CH*LEN)      /* 8388608 */

/* ---------------- scratch (static device globals; allocation-free) -------- */
__device__ float g_xn[NELEM];                /* normalized x; also up_1 / down_1 */
__device__ float g_trend1[NELEM];            /* trend for s=1                     */
__device__ float g_dstack[2 * ROWS * 512];   /* [down ; trend_ds] stacked, max Ls */
__device__ float g_h[2 * ROWS * LEN];        /* GEMM1 output (gelu'd, tf32-rnd)   */
__device__ float g_out8[2 * ROWS * LEN];     /* rows 0..8191: up, 8192..: trend   */
__device__ float g_out4[2 * ROWS * LEN];
__device__ float g_out2[2 * ROWS * LEN];
__device__ float g_means[4 * 2 * ROWS];
__device__ float g_gates[BATCH * 4];
__device__ float g_w1r[1024 * (512 + 256 + 128)];  /* tf32-rounded w1 weights */
__device__ float g_w2r[3 * 1024 * 1024];           /* tf32-rounded w2 weights */

__device__ __forceinline__ float tf32r(float x) {
    uint32_t r;
    asm("cvt.rna.tf32.f32 %0, %1;" : "=r"(r) : "f"(x));
    return __uint_as_float(r);
}

/* ---------------- tf32 rounding pass for weights --------------------------- */
__global__ void round_tf32_kernel(const float* __restrict__ src,
                                  float* __restrict__ dst, int n) {
    int i = blockIdx.x * blockDim.x + threadIdx.x;
    if (i < n) dst[i] = tf32r(src[i]);
}

/* ---------------- BatchNorm over batch axis ------------------------------- */
__global__ void bn_kernel(const float* __restrict__ x,
                          const float* __restrict__ gam,
                          const float* __restrict__ bet) {
    int f = blockIdx.x * blockDim.x + threadIdx.x;
    if (f >= FEAT) return;
    float v[BATCH];
    float s = 0.f;
#pragma unroll
    for (int b = 0; b < BATCH; b++) { v[b] = x[(size_t)b * FEAT + f]; s += v[b]; }
    float mu = s * (1.f / BATCH);
    float q = 0.f;
#pragma unroll
    for (int b = 0; b < BATCH; b++) { float d = v[b] - mu; q += d * d; }
    float inv = rsqrtf(q * (1.f / BATCH) + 1e-5f);
    float gg = gam[f] * inv, bb = bet[f];
#pragma unroll
    for (int b = 0; b < BATCH; b++)
        g_xn[(size_t)b * FEAT + f] = (v[b] - mu) * gg + bb;
}

/* ---------------- depthwise strided conv (tf32-rounded output) ------------ */
__global__ void dwconv_kernel(const float* __restrict__ xn,
                              const float* __restrict__ cw,
                              float* __restrict__ out, int s, int Ls) {
    int idx = blockIdx.x * blockDim.x + threadIdx.x;
    if (idx >= ROWS * Ls) return;
    int t = idx % Ls, row = idx / Ls, c = row % CH;
    const float* xr = xn + (size_t)row * LEN;
    const float* w  = cw + c * 2 * s;
    int base = t * s - s / 2;
    float acc = 0.f;
    for (int k = 0; k < 2 * s; k++) {
        int p = base + k;
        if (p >= 0 && p < LEN) acc = fmaf(xr[p], w[k], acc);
    }
    out[idx] = tf32r(acc);
}

/* ---------------- EMA (reference cumsum formulation) ----------------------- */
__global__ void ema_kernel(const float* __restrict__ src,
                           float* __restrict__ dst,
                           const float* __restrict__ al, int Ls, int rnd) {
    int warp = (blockIdx.x * blockDim.x + threadIdx.x) >> 5;
    int lane = threadIdx.x & 31;
    if (warp >= ROWS) return;
    int c = warp % CH;
    float a  = 1.f / (1.f + expf(-al[c]));
    float om = 1.f - a;
    float l2 = log2f(om);
    const float* x = src + (size_t)warp * Ls;
    float* y       = dst + (size_t)warp * Ls;
    float cnum = 0.f, cden = 0.f;
    for (int j0 = 0; j0 < Ls; j0 += 32) {
        int j = j0 + lane;
        float p = (float)(Ls - 1 - j);
        float base = exp2f(p * l2);
        float wn = (j == 0) ? base : base * a;
        float n = x[j] * wn;
        float d = base;
#pragma unroll
        for (int o = 1; o < 32; o <<= 1) {
            float nn = __shfl_up_sync(0xffffffffu, n, o);
            float dd = __shfl_up_sync(0xffffffffu, d, o);
            if (lane >= o) { n += nn; d += dd; }
        }
        n += cnum; d += cden;
        float v = n / fmaxf(d, 1e-12f);
        y[j] = rnd ? tf32r(v) : v;
        cnum = __shfl_sync(0xffffffffu, n, 31);
        cden = __shfl_sync(0xffffffffu, d, 31);
    }
}

/* ---------------- TF32 tensor-core GEMM, cp.async pipelined --------------- */
/* C[M,N] = A[M,K]*B[N,K]^T. BM=BN=128, BK=16, 2-stage cp.async double buffer.*/
/* smem [row][k] pitch 20 words -> conflict-free m16n8k8 fragment LDS.       */

#define PITCH 20
#define BK 16

__device__ __forceinline__ uint32_t smem_u32(const void* p) {
    uint32_t a;
    asm("{.reg .u64 t; cvta.to.shared.u64 t, %1; cvt.u32.u64 %0, t;}"
        : "=r"(a) : "l"(p));
    return a;
}
__device__ __forceinline__ void cp_async16(uint32_t saddr, const void* g) {
    asm volatile("cp.async.cg.shared.global [%0], [%1], 16;"
                 :: "r"(saddr), "l"(g));
}

__device__ __forceinline__ void mma_tf32(float* d,
                                         const uint32_t* a, const uint32_t* b,
                                         const float* c) {
    asm volatile(
        "mma.sync.aligned.m16n8k8.row.col.f32.tf32.tf32.f32 "
        "{%0,%1,%2,%3}, {%4,%5,%6,%7}, {%8,%9}, {%10,%11,%12,%13};"
        : "=f"(d[0]), "=f"(d[1]), "=f"(d[2]), "=f"(d[3])
        : "r"(a[0]), "r"(a[1]), "r"(a[2]), "r"(a[3]),
          "r"(b[0]), "r"(b[1]),
          "f"(c[0]), "f"(c[1]), "f"(c[2]), "f"(c[3]));
}

__global__ void __launch_bounds__(256, 2)
gemm_tc_kernel(const float* __restrict__ A, const float* __restrict__ B,
               float* __restrict__ C, const float* __restrict__ bias,
               int K, int act) {
    __shared__ float As[2][128 * PITCH];
    __shared__ float Bs[2][128 * PITCH];
    const int N = 1024;
    const int tid  = threadIdx.x;
    const int wid  = tid >> 5;
    const int lane = tid & 31;
    const int g    = lane >> 2;
    const int tg   = lane & 3;
    const int wm   = (wid >> 1) * 32;
    const int wn   = (wid & 1) * 64;
    const int m0 = blockIdx.y * 128, n0 = blockIdx.x * 128;

    /* loader: thread t -> row = t>>1, k-base = (t&1)*8, two 16B chunks */
    const int lrow = tid >> 1;
    const int lb   = (tid & 1) * 8;
    const float* gA = A + (size_t)(m0 + lrow) * K + lb;
    const float* gB = B + (size_t)(n0 + lrow) * K + lb;
    const uint32_t sA = smem_u32(&As[0][lrow * PITCH + lb]);
    const uint32_t sB = smem_u32(&Bs[0][lrow * PITCH + lb]);
    const uint32_t bufoff = 128 * PITCH * 4;

    float acc[2][8][4];
#pragma unroll
    for (int i = 0; i < 2; i++)
#pragma unroll
        for (int j = 0; j < 8; j++)
#pragma unroll
            for (int q = 0; q < 4; q++) acc[i][j][q] = 0.f;

    const int niter = K / BK;

    /* prologue: stage 0 */
    cp_async16(sA, gA);      cp_async16(sA + 16, gA + 4);
    cp_async16(sB, gB);      cp_async16(sB + 16, gB + 4);
    asm volatile("cp.async.commit_group;");

    for (int i = 0; i < niter; i++) {
        if (i + 1 < niter) {
            int off = (i + 1) * BK;
            uint32_t d = ((i + 1) & 1) * bufoff;
            cp_async16(sA + d, gA + off);      cp_async16(sA + d + 16, gA + off + 4);
            cp_async16(sB + d, gB + off);      cp_async16(sB + d + 16, gB + off + 4);
            asm volatile("cp.async.commit_group;");
            asm volatile("cp.async.wait_group 1;");
        } else {
            asm volatile("cp.async.wait_group 0;");
        }
        __syncthreads();

        const uint32_t* as = (const uint32_t*)As[i & 1];
        const uint32_t* bs = (const uint32_t*)Bs[i & 1];
#pragma unroll
        for (int kk = 0; kk < BK; kk += 8) {
            uint32_t af[2][4], bf[8][2];
#pragma unroll
            for (int mt = 0; mt < 2; mt++) {
                int mb = (wm + mt * 16 + g) * PITCH + kk + tg;
                af[mt][0] = as[mb];
                af[mt][1] = as[mb + 8 * PITCH];
                af[mt][2] = as[mb + 4];
                af[mt][3] = as[mb + 8 * PITCH + 4];
            }
#pragma unroll
            for (int nt = 0; nt < 8; nt++) {
                int nb = (wn + nt * 8 + g) * PITCH + kk + tg;
                bf[nt][0] = bs[nb];
                bf[nt][1] = bs[nb + 4];
            }
#pragma unroll
            for (int mt = 0; mt < 2; mt++)
#pragma unroll
                for (int nt = 0; nt < 8; nt++)
                    mma_tf32(acc[mt][nt], af[mt], bf[nt], acc[mt][nt]);
        }
        __syncthreads();
    }

    /* epilogue: bias (+ exact gelu, tf32-rounded since h feeds next GEMM) */
#pragma unroll
    for (int mt = 0; mt < 2; mt++) {
        int r0 = m0 + wm + mt * 16 + g;
#pragma unroll
        for (int nt = 0; nt < 8; nt++) {
            int c0 = n0 + wn + nt * 8 + 2 * tg;
            float b0 = bias[c0], b1 = bias[c0 + 1];
            float v0 = acc[mt][nt][0] + b0;
            float v1 = acc[mt][nt][1] + b1;
            float v2 = acc[mt][nt][2] + b0;
            float v3 = acc[mt][nt][3] + b1;
            if (act) {
                v0 = tf32r(0.5f * v0 * (1.f + erff(v0 * 0.70710678118654752f)));
                v1 = tf32r(0.5f * v1 * (1.f + erff(v1 * 0.70710678118654752f)));
                v2 = tf32r(0.5f * v2 * (1.f + erff(v2 * 0.70710678118654752f)));
                v3 = tf32r(0.5f * v3 * (1.f + erff(v3 * 0.70710678118654752f)));
            }
            *(float2*)(C + (size_t)r0 * N + c0)       = make_float2(v0, v1);
            *(float2*)(C + (size_t)(r0 + 8) * N + c0) = make_float2(v2, v3);
        }
    }
}

/* ---------------- per-row mean over L -------------------------------------- */
__global__ void rowmean_kernel(const float* __restrict__ src,
                               float* __restrict__ dst) {
    int row = blockIdx.x;
    const float* p = src + (size_t)row * LEN;
    float s = 0.f;
    for (int i = threadIdx.x; i < LEN; i += 256) s += p[i];
    __shared__ float sm[256];
    sm[threadIdx.x] = s; __syncthreads();
    for (int o = 128; o > 0; o >>= 1) {
        if (threadIdx.x < o) sm[threadIdx.x] += sm[threadIdx.x + o];
        __syncthreads();
    }
    if (threadIdx.x == 0) dst[row] = sm[0] * (1.f / LEN);
}

/* ---------------- gates ----------------------------------------------------- */
__global__ void gate_kernel(const float* __restrict__ gw8, const float* __restrict__ gb8,
                            const float* __restrict__ gw4, const float* __restrict__ gb4,
                            const float* __restrict__ gw2, const float* __restrict__ gb2,
                            const float* __restrict__ gw1, const float* __restrict__ gb1) {
    int b = blockIdx.x;
    int c = threadIdx.x;
    __shared__ float red[4][128];
    const float* gws[4] = {gw8, gw4, gw2, gw1};
    for (int s = 0; s < 4; s++) {
        float um = g_means[(s * 2 + 0) * ROWS + b * CH + c];
        float tm = g_means[(s * 2 + 1) * ROWS + b * CH + c];
        red[s][c] = (um - tm) * gws[s][c];
    }
    __syncthreads();
    for (int o = 64; o > 0; o >>= 1) {
        if (c < o) {
            for (int s = 0; s < 4; s++) red[s][c] += red[s][c + o];
        }
        __syncthreads();
    }
    if (c == 0) {
        float gbv[4] = {gb8[0], gb4[0], gb2[0], gb1[0]};
        float gv[4], tot = 0.f;
        for (int s = 0; s < 4; s++) {
            gv[s] = 1.f / (1.f + expf(-(red[s][0] + gbv[s])));
            tot += gv[s];
        }
        for (int s = 0; s < 4; s++) g_gates[b * 4 + s] = gv[s] / (tot + 1e-6f);
    }
}

/* ---------------- final weighted combine; out = [season ; trend] ----------- */
__global__ void combine_kernel(float* __restrict__ out) {
    size_t idx = blockIdx.x * (size_t)blockDim.x + threadIdx.x;
    if (idx >= NELEM) return;
    int b = (int)(idx >> 10) / CH;
    const float* G = g_gates + b * 4;
    float g0 = G[0], g1 = G[1], g2 = G[2], g3 = G[3];
    float u8 = g_out8[idx], t8 = g_out8[idx + (size_t)NELEM];
    float u4 = g_out4[idx], t4 = g_out4[idx + (size_t)NELEM];
    float u2 = g_out2[idx], t2 = g_out2[idx + (size_t)NELEM];
    float u1 = g_xn[idx],   t1 = g_trend1[idx];
    float trend  = g0 * t8 + g1 * t4 + g2 * t2 + g3 * t1;
    float season = g0 * (u8 - t8) + g1 * (u4 - t4) + g2 * (u2 - t2) + g3 * (u1 - t1);
    out[idx] = season;
    out[(size_t)NELEM + idx] = trend;
}

/* ---------------- host orchestration -------------------------------------- */
extern "C" void kernel_launch(void* const* d_in, const int* in_sizes, int n_in,
                              void* d_out, int out_size) {
    const float* x    = (const float*)d_in[0];
    const float* bng  = (const float*)d_in[1];
    const float* bnb  = (const float*)d_in[2];
    const float* cw8  = (const float*)d_in[3];
    const float* w1_8 = (const float*)d_in[4];
    const float* b1_8 = (const float*)d_in[5];
    const float* w2_8 = (const float*)d_in[6];
    const float* b2_8 = (const float*)d_in[7];
    const float* cw4  = (const float*)d_in[8];
    const float* w1_4 = (const float*)d_in[9];
    const float* b1_4 = (const float*)d_in[10];
    const float* w2_4 = (const float*)d_in[11];
    const float* b2_4 = (const float*)d_in[12];
    const float* cw2  = (const float*)d_in[13];
    const float* w1_2 = (const float*)d_in[14];
    const float* b1_2 = (const float*)d_in[15];
    const float* w2_2 = (const float*)d_in[16];
    const float* b2_2 = (const float*)d_in[17];
    const float* gw8  = (const float*)d_in[18];
    const float* gb8  = (const float*)d_in[19];
    const float* al8  = (const float*)d_in[20];
    const float* gw4  = (const float*)d_in[21];
    const float* gb4  = (const float*)d_in[22];
    const float* al4  = (const float*)d_in[23];
    const float* gw2  = (const float*)d_in[24];
    const float* gb2  = (const float*)d_in[25];
    const float* al2  = (const float*)d_in[26];
    const float* gw1  = (const float*)d_in[27];
    const float* gb1  = (const float*)d_in[28];
    const float* al1  = (const float*)d_in[29];
    float* out = (float*)d_out;

    float *xn, *tr1, *dst, *h, *o8, *o4, *o2, *means, *w1r, *w2r;
    cudaGetSymbolAddress((void**)&xn,    g_xn);
    cudaGetSymbolAddress((void**)&tr1,   g_trend1);
    cudaGetSymbolAddress((void**)&dst,   g_dstack);
    cudaGetSymbolAddress((void**)&h,     g_h);
    cudaGetSymbolAddress((void**)&o8,    g_out8);
    cudaGetSymbolAddress((void**)&o4,    g_out4);
    cudaGetSymbolAddress((void**)&o2,    g_out2);
    cudaGetSymbolAddress((void**)&means, g_means);
    cudaGetSymbolAddress((void**)&w1r,   g_w1r);
    cudaGetSymbolAddress((void**)&w2r,   g_w2r);

    float* w1r8 = w1r;                    /* 1024*128 */
    float* w1r4 = w1r + 1024 * 128;       /* 1024*256 */
    float* w1r2 = w1r + 1024 * (128+256); /* 1024*512 */
    float* w2r8 = w2r;
    float* w2r4 = w2r + 1024 * 1024;
    float* w2r2 = w2r + 2 * 1024 * 1024;

    /* weight rounding (tiny) */
    round_tf32_kernel<<<(1024*128 + 255)/256, 256>>>(w1_8, w1r8, 1024*128);
    round_tf32_kernel<<<(1024*256 + 255)/256, 256>>>(w1_4, w1r4, 1024*256);
    round_tf32_kernel<<<(1024*512 + 255)/256, 256>>>(w1_2, w1r2, 1024*512);
    round_tf32_kernel<<<(1024*1024 + 255)/256, 256>>>(w2_8, w2r8, 1024*1024);
    round_tf32_kernel<<<(1024*1024 + 255)/256, 256>>>(w2_4, w2r4, 1024*1024);
    round_tf32_kernel<<<(1024*1024 + 255)/256, 256>>>(w2_2, w2r2, 1024*1024);

    /* BatchNorm */
    bn_kernel<<<FEAT / 256, 256>>>(x, bng, bnb);

    /* s = 1 branch: trend1 = EMA(xn), full precision */
    ema_kernel<<<ROWS / 8, 256>>>(xn, tr1, al1, LEN, 0);

    /* s = 8 */
    {
        const int Ls = 128;
        dwconv_kernel<<<(ROWS * Ls + 255) / 256, 256>>>(xn, cw8, dst, 8, Ls);
        ema_kernel<<<ROWS / 8, 256>>>(dst, dst + (size_t)ROWS * Ls, al8, Ls, 1);
        gemm_tc_kernel<<<dim3(8, 128), 256>>>(dst, w1r8, h, b1_8, Ls, 1);
        gemm_tc_kernel<<<dim3(8, 128), 256>>>(h, w2r8, o8, b2_8, 1024, 0);
    }
    /* s = 4 */
    {
        const int Ls = 256;
        dwconv_kernel<<<(ROWS * Ls + 255) / 256, 256>>>(xn, cw4, dst, 4, Ls);
        ema_kernel<<<ROWS / 8, 256>>>(dst, dst + (size_t)ROWS * Ls, al4, Ls, 1);
        gemm_tc_kernel<<<dim3(8, 128), 256>>>(dst, w1r4, h, b1_4, Ls, 1);
        gemm_tc_kernel<<<dim3(8, 128), 256>>>(h, w2r4, o4, b2_4, 1024, 0);
    }
    /* s = 2 */
    {
        const int Ls = 512;
        dwconv_kernel<<<(ROWS * Ls + 255) / 256, 256>>>(xn, cw2, dst, 2, Ls);
        ema_kernel<<<ROWS / 8, 256>>>(dst, dst + (size_t)ROWS * Ls, al2, Ls, 1);
        gemm_tc_kernel<<<dim3(8, 128), 256>>>(dst, w1r2, h, b1_2, Ls, 1);
        gemm_tc_kernel<<<dim3(8, 128), 256>>>(h, w2r2, o2, b2_2, 1024, 0);
    }

    /* per-row means (up & trend) for gating */
    rowmean_kernel<<<2 * ROWS, 256>>>(o8, means + 0 * 2 * ROWS);
    rowmean_kernel<<<2 * ROWS, 256>>>(o4, means + 1 * 2 * ROWS);
    rowmean_kernel<<<2 * ROWS, 256>>>(o2, means + 2 * 2 * ROWS);
    rowmean_kernel<<<ROWS, 256>>>(xn,  means + 3 * 2 * ROWS);
    rowmean_kernel<<<ROWS, 256>>>(tr1, means + 3 * 2 * ROWS + ROWS);

    gate_kernel<<<BATCH, 128>>>(gw8, gb8, gw4, gb4, gw2, gb2, gw1, gb1);

    combine_kernel<<<(NELEM + 255) / 256, 256>>>(out);
}

// round 5
// speedup vs baseline: 2.5737x; 1.0383x over previous
#include <cuda_runtime.h>
#include <math.h>
#include <stdint.h>

#define BATCH 64
#define CH    128
#define LEN   1024
#define ROWS  (BATCH*CH)          /* 8192  */
#define FEAT  (CH*LEN)            /* 131072 */
#define NELEM (BATCH*CH*LEN)      /* 8388608 */

/* ---------------- scratch (static device globals; allocation-free) -------- */
__device__ float g_xn[NELEM];
__device__ float g_trend1[NELEM];
__device__ float g_dstack[2 * ROWS * 512];
__device__ float g_h[2 * ROWS * LEN];
__device__ float g_out8[2 * ROWS * LEN];
__device__ float g_out4[2 * ROWS * LEN];
__device__ float g_out2[2 * ROWS * LEN];
__device__ float g_means[4 * 2 * ROWS];
__device__ float g_gates[BATCH * 4];
__device__ float g_w1r[1024 * (512 + 256 + 128)];
__device__ float g_w2r[3 * 1024 * 1024];

__device__ __forceinline__ float tf32r(float x) {
    uint32_t r;
    asm("cvt.rna.tf32.f32 %0, %1;" : "=r"(r) : "f"(x));
    return __uint_as_float(r);
}

__global__ void round_tf32_kernel(const float* __restrict__ src,
                                  float* __restrict__ dst, int n) {
    int i = blockIdx.x * blockDim.x + threadIdx.x;
    if (i < n) dst[i] = tf32r(src[i]);
}

/* ---------------- BatchNorm over batch axis ------------------------------- */
__global__ void bn_kernel(const float* __restrict__ x,
                          const float* __restrict__ gam,
                          const float* __restrict__ bet) {
    int f = blockIdx.x * blockDim.x + threadIdx.x;
    if (f >= FEAT) return;
    float v[BATCH];
    float s = 0.f;
#pragma unroll
    for (int b = 0; b < BATCH; b++) { v[b] = x[(size_t)b * FEAT + f]; s += v[b]; }
    float mu = s * (1.f / BATCH);
    float q = 0.f;
#pragma unroll
    for (int b = 0; b < BATCH; b++) { float d = v[b] - mu; q += d * d; }
    float inv = rsqrtf(q * (1.f / BATCH) + 1e-5f);
    float gg = gam[f] * inv, bb = bet[f];
#pragma unroll
    for (int b = 0; b < BATCH; b++)
        g_xn[(size_t)b * FEAT + f] = (v[b] - mu) * gg + bb;
}

/* ---------------- depthwise strided conv (tf32-rounded output) ------------ */
__global__ void dwconv_kernel(const float* __restrict__ xn,
                              const float* __restrict__ cw,
                              float* __restrict__ out, int s, int Ls) {
    int idx = blockIdx.x * blockDim.x + threadIdx.x;
    if (idx >= ROWS * Ls) return;
    int t = idx % Ls, row = idx / Ls, c = row % CH;
    const float* xr = xn + (size_t)row * LEN;
    const float* w  = cw + c * 2 * s;
    int base = t * s - s / 2;
    float acc = 0.f;
    for (int k = 0; k < 2 * s; k++) {
        int p = base + k;
        if (p >= 0 && p < LEN) acc = fmaf(xr[p], w[k], acc);
    }
    out[idx] = tf32r(acc);
}

/* ---------------- EMA (reference cumsum formulation) ----------------------- */
__global__ void ema_kernel(const float* __restrict__ src,
                           float* __restrict__ dst,
                           const float* __restrict__ al, int Ls, int rnd) {
    int warp = (blockIdx.x * blockDim.x + threadIdx.x) >> 5;
    int lane = threadIdx.x & 31;
    if (warp >= ROWS) return;
    int c = warp % CH;
    float a  = 1.f / (1.f + expf(-al[c]));
    float om = 1.f - a;
    float l2 = log2f(om);
    const float* x = src + (size_t)warp * Ls;
    float* y       = dst + (size_t)warp * Ls;
    float cnum = 0.f, cden = 0.f;
    for (int j0 = 0; j0 < Ls; j0 += 32) {
        int j = j0 + lane;
        float p = (float)(Ls - 1 - j);
        float base = exp2f(p * l2);
        float wn = (j == 0) ? base : base * a;
        float n = x[j] * wn;
        float d = base;
#pragma unroll
        for (int o = 1; o < 32; o <<= 1) {
            float nn = __shfl_up_sync(0xffffffffu, n, o);
            float dd = __shfl_up_sync(0xffffffffu, d, o);
            if (lane >= o) { n += nn; d += dd; }
        }
        n += cnum; d += cden;
        float v = n / fmaxf(d, 1e-12f);
        y[j] = rnd ? tf32r(v) : v;
        cnum = __shfl_sync(0xffffffffu, n, 31);
        cden = __shfl_sync(0xffffffffu, d, 31);
    }
}

/* ================== GEMM  C[M,N=1024] = A[M,K]*B[N,K]^T ==================== */
/* Arch-feature dual path:                                                     */
/*   sm_103a pass  -> tcgen05 kind::tf32, TMEM accumulate, cp.async 3-stage   */
/*   plain sm_103  -> mma.sync tf32 (round-3 proven), same symbol             */

#define STAGES 3
#define SMEM_MBAR0 16
#define SMEM_MBAR1 24
#define SMEM_TILES 1024
#define STAGE_BYTES 32768           /* A 16KB + B 16KB */
#define GEMM_SMEM (SMEM_TILES + STAGES * STAGE_BYTES)

#define DESC_SW128 ((2ULL << 61) | (1ULL << 46) | (64ULL << 32) | (1ULL << 16))
#define IDESC_TF32 0x8200910u       /* dtype=F32, a/b=TF32, N=128, M=128 */

#define PITCH 20
#define BK 16

#if defined(__CUDA_ARCH__) && (defined(__CUDA_ARCH_FEAT_SM103_ALL) || \
    (defined(__CUDA_ARCH_SPECIFIC__) && (__CUDA_ARCH_SPECIFIC__ == 1030)))
#define HAS_TCGEN05 1
#else
#define HAS_TCGEN05 0
#endif

__device__ __forceinline__ uint32_t smem_u32(const void* p) {
    uint32_t a;
    asm("{.reg .u64 t; cvta.to.shared.u64 t, %1; cvt.u32.u64 %0, t;}"
        : "=r"(a) : "l"(p));
    return a;
}
__device__ __forceinline__ void cp_async16(uint32_t saddr, const void* g) {
    asm volatile("cp.async.cg.shared.global [%0], [%1], 16;"
                 :: "r"(saddr), "l"(g));
}
__device__ __forceinline__ void mma_tf32(float* d,
                                         const uint32_t* a, const uint32_t* b,
                                         const float* c) {
    asm volatile(
        "mma.sync.aligned.m16n8k8.row.col.f32.tf32.tf32.f32 "
        "{%0,%1,%2,%3}, {%4,%5,%6,%7}, {%8,%9}, {%10,%11,%12,%13};"
        : "=f"(d[0]), "=f"(d[1]), "=f"(d[2]), "=f"(d[3])
        : "r"(a[0]), "r"(a[1]), "r"(a[2]), "r"(a[3]),
          "r"(b[0]), "r"(b[1]),
          "f"(c[0]), "f"(c[1]), "f"(c[2]), "f"(c[3]));
}

/* tcgen05 ops as macros so the asm text exists ONLY in the 'a' pass */
#define TC5_ALLOC(sb, n) \
    asm volatile("tcgen05.alloc.cta_group::1.sync.aligned.shared::cta.b32 [%0], %1;" \
                 :: "r"(sb), "r"(n) : "memory")
#define TC5_RELINQ() \
    asm volatile("tcgen05.relinquish_alloc_permit.cta_group::1.sync.aligned;")
#define TC5_DEALLOC(t, n) \
    asm volatile("tcgen05.dealloc.cta_group::1.sync.aligned.b32 %0, %1;" :: "r"(t), "r"(n))
#define TC5_MMA(d, ad, bd, en) \
    asm volatile("{.reg .pred p; setp.ne.u32 p, %4, 0;\n\t" \
        "tcgen05.mma.cta_group::1.kind::tf32 [%0], %1, %2, %3, {%5,%5,%5,%5}, p;}\n" \
        :: "r"(d), "l"(ad), "l"(bd), "r"(IDESC_TF32), "r"(en), "r"(0u) : "memory")
#define TC5_COMMIT(mb) \
    asm volatile("tcgen05.commit.cta_group::1.mbarrier::arrive::one.shared::cluster.b64 [%0];" \
                 :: "r"(mb) : "memory")
#define TC5_FENCE_AFTER()  asm volatile("tcgen05.fence::after_thread_sync;" ::: "memory")
#define TC5_WAIT_LD()      asm volatile("tcgen05.wait::ld.sync.aligned;" ::: "memory")
#define TC5_LD32(r, addr) \
    asm volatile("tcgen05.ld.sync.aligned.32x32b.x32.b32 " \
        "{%0,%1,%2,%3,%4,%5,%6,%7,%8,%9,%10,%11,%12,%13,%14,%15," \
        "%16,%17,%18,%19,%20,%21,%22,%23,%24,%25,%26,%27,%28,%29,%30,%31}, [%32];" \
        : "=r"((r)[0]), "=r"((r)[1]), "=r"((r)[2]), "=r"((r)[3]), \
          "=r"((r)[4]), "=r"((r)[5]), "=r"((r)[6]), "=r"((r)[7]), \
          "=r"((r)[8]), "=r"((r)[9]), "=r"((r)[10]), "=r"((r)[11]), \
          "=r"((r)[12]), "=r"((r)[13]), "=r"((r)[14]), "=r"((r)[15]), \
          "=r"((r)[16]), "=r"((r)[17]), "=r"((r)[18]), "=r"((r)[19]), \
          "=r"((r)[20]), "=r"((r)[21]), "=r"((r)[22]), "=r"((r)[23]), \
          "=r"((r)[24]), "=r"((r)[25]), "=r"((r)[26]), "=r"((r)[27]), \
          "=r"((r)[28]), "=r"((r)[29]), "=r"((r)[30]), "=r"((r)[31]) \
        : "r"(addr))
#define MBAR_INIT(a, c) \
    asm volatile("mbarrier.init.shared.b64 [%0], %1;" :: "r"(a), "r"(c) : "memory")
#define MBAR_WAIT(a, par) do { \
    uint32_t _done; \
    asm volatile("{.reg .pred p;\n\t" \
        "mbarrier.try_wait.parity.acquire.cta.shared::cta.b64 p, [%1], %2;\n\t" \
        "selp.b32 %0, 1, 0, p;}" : "=r"(_done) : "r"(a), "r"(par) : "memory"); \
    if (!_done) { \
        asm volatile("{.reg .pred P1;\n\t" \
            "W_%=:\n\t" \
            "mbarrier.try_wait.parity.acquire.cta.shared::cta.b64 P1, [%0], %1, 0x989680;\n\t" \
            "@P1 bra.uni D_%=;\n\t" \
            "bra.uni W_%=;\n\t" \
            "D_%=:\n\t}" :: "r"(a), "r"(par) : "memory"); \
    } } while (0)

__device__ __forceinline__ float bias_gelu(float v, int act) {
    if (act) v = tf32r(0.5f * v * (1.f + erff(v * 0.70710678118654752f)));
    return v;
}

__global__ void __launch_bounds__(256)
gemm_tc_kernel(const float* __restrict__ A, const float* __restrict__ B,
               float* __restrict__ C, const float* __restrict__ bias,
               int K, int act) {
    extern __shared__ char smem[];
    const int tid = threadIdx.x, wid = tid >> 5, lane = tid & 31;
    const int m0 = blockIdx.y * 128, n0 = blockIdx.x * 128;

#if HAS_TCGEN05
    /* ===================== tcgen05 kind::tf32 path ======================== */
    const uint32_t sb = smem_u32(smem);
    if (wid == 0) {
        uint32_t e;
        asm volatile("{.reg .pred p; elect.sync _|p, 0xFFFFFFFF; selp.b32 %0,1,0,p;}"
                     : "=r"(e));
        (void)e;
        TC5_ALLOC(sb, 128u);
        TC5_RELINQ();
    }
    if (tid == 0) { MBAR_INIT(sb + SMEM_MBAR0, 1); MBAR_INIT(sb + SMEM_MBAR1, 1); }
    __syncthreads();
    uint32_t tmem;
    asm volatile("ld.shared.b32 %0, [%1];" : "=r"(tmem) : "r"(sb));

    const int mat = tid >> 7, row = tid & 127;
    const float* src = mat ? (B + (size_t)(n0 + row) * K)
                           : (A + (size_t)(m0 + row) * K);
    const uint32_t matoff = mat * 16384;
    const int nch = K / 32;

#pragma unroll
    for (int pc = 0; pc < 2; pc++) {
        uint32_t base = sb + SMEM_TILES + pc * STAGE_BYTES + matoff;
        const float* g = src + pc * 32;
#pragma unroll
        for (int c = 0; c < 8; c++) {
            uint32_t off = row * 128 + c * 16;
            cp_async16(base + (off ^ ((off >> 3) & 0x70)), g + c * 4);
        }
        asm volatile("cp.async.commit_group;");
    }

    for (int i = 0; i < nch; i++) {
        asm volatile("cp.async.wait_group 1;");
        __syncthreads();
        if (wid == 0) {
            uint32_t e;
            asm volatile("{.reg .pred p; elect.sync _|p, 0xFFFFFFFF; selp.b32 %0,1,0,p;}"
                         : "=r"(e));
            if (e) {
                asm volatile("fence.proxy.async.shared::cta;" ::: "memory");
                TC5_FENCE_AFTER();
                uint32_t sa = sb + SMEM_TILES + (i % STAGES) * STAGE_BYTES;
                uint64_t ad = DESC_SW128 | ((uint64_t)(sa >> 4) & 0x3FFF);
                uint64_t bd = DESC_SW128 | ((uint64_t)((sa + 16384) >> 4) & 0x3FFF);
#pragma unroll
                for (int j = 0; j < 4; j++)
                    TC5_MMA(tmem, ad + j * 2, bd + j * 2, (uint32_t)(i > 0 || j > 0));
                TC5_COMMIT(sb + ((i & 1) ? SMEM_MBAR1 : SMEM_MBAR0));
            }
        }
        if (i >= 1) {
            int j = i - 1;
            MBAR_WAIT(sb + ((j & 1) ? SMEM_MBAR1 : SMEM_MBAR0), (uint32_t)((j >> 1) & 1));
        }
        if (i + 2 < nch) {
            uint32_t base = sb + SMEM_TILES + ((i + 2) % STAGES) * STAGE_BYTES + matoff;
            const float* g = src + (i + 2) * 32;
#pragma unroll
            for (int c = 0; c < 8; c++) {
                uint32_t off = row * 128 + c * 16;
                cp_async16(base + (off ^ ((off >> 3) & 0x70)), g + c * 4);
            }
        }
        asm volatile("cp.async.commit_group;");
    }
    {
        int j = nch - 1;
        MBAR_WAIT(sb + ((j & 1) ? SMEM_MBAR1 : SMEM_MBAR0), (uint32_t)((j >> 1) & 1));
    }
    TC5_FENCE_AFTER();

    const int sub = wid & 3;
    const int cb  = (wid >> 2) * 64;
    const int m   = m0 + sub * 32 + lane;
#pragma unroll
    for (int p = 0; p < 2; p++) {
        uint32_t r[32];
        TC5_LD32(r, tmem + cb + p * 32);
        TC5_WAIT_LD();
        int ncol = n0 + cb + p * 32;
#pragma unroll
        for (int c = 0; c < 32; c += 4) {
            float4 v;
            v.x = bias_gelu(__uint_as_float(r[c + 0]) + bias[ncol + c + 0], act);
            v.y = bias_gelu(__uint_as_float(r[c + 1]) + bias[ncol + c + 1], act);
            v.z = bias_gelu(__uint_as_float(r[c + 2]) + bias[ncol + c + 2], act);
            v.w = bias_gelu(__uint_as_float(r[c + 3]) + bias[ncol + c + 3], act);
            *(float4*)(C + (size_t)m * 1024 + ncol + c) = v;
        }
    }
    __syncthreads();
    if (wid == 0) TC5_DEALLOC(tmem, 128u);

#else
    /* ===================== mma.sync tf32 fallback ========================= */
    float* AsBuf = (float*)smem;                 /* 2 x 2560 floats */
    float* BsBuf = (float*)smem + 2 * 128 * PITCH;
    const int g    = lane >> 2;
    const int tg   = lane & 3;
    const int wm   = (wid >> 1) * 32;
    const int wn   = (wid & 1) * 64;

    const int lrow = tid >> 1;
    const int lb   = (tid & 1) * 8;
    const float* gA = A + (size_t)(m0 + lrow) * K + lb;
    const float* gB = B + (size_t)(n0 + lrow) * K + lb;
    const uint32_t sA = smem_u32(&AsBuf[lrow * PITCH + lb]);
    const uint32_t sB = smem_u32(&BsBuf[lrow * PITCH + lb]);
    const uint32_t bufoff = 128 * PITCH * 4;

    float acc[2][8][4];
#pragma unroll
    for (int i = 0; i < 2; i++)
#pragma unroll
        for (int j = 0; j < 8; j++)
#pragma unroll
            for (int q = 0; q < 4; q++) acc[i][j][q] = 0.f;

    const int niter = K / BK;
    cp_async16(sA, gA);      cp_async16(sA + 16, gA + 4);
    cp_async16(sB, gB);      cp_async16(sB + 16, gB + 4);
    asm volatile("cp.async.commit_group;");

    for (int i = 0; i < niter; i++) {
        if (i + 1 < niter) {
            int off = (i + 1) * BK;
            uint32_t d = ((i + 1) & 1) * bufoff;
            cp_async16(sA + d, gA + off);      cp_async16(sA + d + 16, gA + off + 4);
            cp_async16(sB + d, gB + off);      cp_async16(sB + d + 16, gB + off + 4);
            asm volatile("cp.async.commit_group;");
            asm volatile("cp.async.wait_group 1;");
        } else {
            asm volatile("cp.async.wait_group 0;");
        }
        __syncthreads();

        const uint32_t* as = (const uint32_t*)(AsBuf + (i & 1) * 128 * PITCH);
        const uint32_t* bs = (const uint32_t*)(BsBuf + (i & 1) * 128 * PITCH);
#pragma unroll
        for (int kk = 0; kk < BK; kk += 8) {
            uint32_t af[2][4], bf[8][2];
#pragma unroll
            for (int mt = 0; mt < 2; mt++) {
                int mb = (wm + mt * 16 + g) * PITCH + kk + tg;
                af[mt][0] = as[mb];
                af[mt][1] = as[mb + 8 * PITCH];
                af[mt][2] = as[mb + 4];
                af[mt][3] = as[mb + 8 * PITCH + 4];
            }
#pragma unroll
            for (int nt = 0; nt < 8; nt++) {
                int nb = (wn + nt * 8 + g) * PITCH + kk + tg;
                bf[nt][0] = bs[nb];
                bf[nt][1] = bs[nb + 4];
            }
#pragma unroll
            for (int mt = 0; mt < 2; mt++)
#pragma unroll
                for (int nt = 0; nt < 8; nt++)
                    mma_tf32(acc[mt][nt], af[mt], bf[nt], acc[mt][nt]);
        }
        __syncthreads();
    }

#pragma unroll
    for (int mt = 0; mt < 2; mt++) {
        int r0 = m0 + wm + mt * 16 + g;
#pragma unroll
        for (int nt = 0; nt < 8; nt++) {
            int c0 = n0 + wn + nt * 8 + 2 * tg;
            float b0 = bias[c0], b1 = bias[c0 + 1];
            float v0 = bias_gelu(acc[mt][nt][0] + b0, act);
            float v1 = bias_gelu(acc[mt][nt][1] + b1, act);
            float v2 = bias_gelu(acc[mt][nt][2] + b0, act);
            float v3 = bias_gelu(acc[mt][nt][3] + b1, act);
            *(float2*)(C + (size_t)r0 * 1024 + c0)       = make_float2(v0, v1);
            *(float2*)(C + (size_t)(r0 + 8) * 1024 + c0) = make_float2(v2, v3);
        }
    }
#endif
}

/* ---------------- per-row mean over L -------------------------------------- */
__global__ void rowmean_kernel(const float* __restrict__ src,
                               float* __restrict__ dst) {
    int row = blockIdx.x;
    const float* p = src + (size_t)row * LEN;
    float s = 0.f;
    for (int i = threadIdx.x; i < LEN; i += 256) s += p[i];
    __shared__ float sm[256];
    sm[threadIdx.x] = s; __syncthreads();
    for (int o = 128; o > 0; o >>= 1) {
        if (threadIdx.x < o) sm[threadIdx.x] += sm[threadIdx.x + o];
        __syncthreads();
    }
    if (threadIdx.x == 0) dst[row] = sm[0] * (1.f / LEN);
}

/* ---------------- gates ----------------------------------------------------- */
__global__ void gate_kernel(const float* __restrict__ gw8, const float* __restrict__ gb8,
                            const float* __restrict__ gw4, const float* __restrict__ gb4,
                            const float* __restrict__ gw2, const float* __restrict__ gb2,
                            const float* __restrict__ gw1, const float* __restrict__ gb1) {
    int b = blockIdx.x;
    int c = threadIdx.x;
    __shared__ float red[4][128];
    const float* gws[4] = {gw8, gw4, gw2, gw1};
    for (int s = 0; s < 4; s++) {
        float um = g_means[(s * 2 + 0) * ROWS + b * CH + c];
        float tm = g_means[(s * 2 + 1) * ROWS + b * CH + c];
        red[s][c] = (um - tm) * gws[s][c];
    }
    __syncthreads();
    for (int o = 64; o > 0; o >>= 1) {
        if (c < o) {
            for (int s = 0; s < 4; s++) red[s][c] += red[s][c + o];
        }
        __syncthreads();
    }
    if (c == 0) {
        float gbv[4] = {gb8[0], gb4[0], gb2[0], gb1[0]};
        float gv[4], tot = 0.f;
        for (int s = 0; s < 4; s++) {
            gv[s] = 1.f / (1.f + expf(-(red[s][0] + gbv[s])));
            tot += gv[s];
        }
        for (int s = 0; s < 4; s++) g_gates[b * 4 + s] = gv[s] / (tot + 1e-6f);
    }
}

/* ---------------- final weighted combine; out = [season ; trend] ----------- */
__global__ void combine_kernel(float* __restrict__ out) {
    size_t idx = blockIdx.x * (size_t)blockDim.x + threadIdx.x;
    if (idx >= NELEM) return;
    int b = (int)(idx >> 10) / CH;
    const float* G = g_gates + b * 4;
    float g0 = G[0], g1 = G[1], g2 = G[2], g3 = G[3];
    float u8 = g_out8[idx], t8 = g_out8[idx + (size_t)NELEM];
    float u4 = g_out4[idx], t4 = g_out4[idx + (size_t)NELEM];
    float u2 = g_out2[idx], t2 = g_out2[idx + (size_t)NELEM];
    float u1 = g_xn[idx],   t1 = g_trend1[idx];
    float trend  = g0 * t8 + g1 * t4 + g2 * t2 + g3 * t1;
    float season = g0 * (u8 - t8) + g1 * (u4 - t4) + g2 * (u2 - t2) + g3 * (u1 - t1);
    out[idx] = season;
    out[(size_t)NELEM + idx] = trend;
}

/* ---------------- host orchestration -------------------------------------- */
extern "C" void kernel_launch(void* const* d_in, const int* in_sizes, int n_in,
                              void* d_out, int out_size) {
    const float* x    = (const float*)d_in[0];
    const float* bng  = (const float*)d_in[1];
    const float* bnb  = (const float*)d_in[2];
    const float* cw8  = (const float*)d_in[3];
    const float* w1_8 = (const float*)d_in[4];
    const float* b1_8 = (const float*)d_in[5];
    const float* w2_8 = (const float*)d_in[6];
    const float* b2_8 = (const float*)d_in[7];
    const float* cw4  = (const float*)d_in[8];
    const float* w1_4 = (const float*)d_in[9];
    const float* b1_4 = (const float*)d_in[10];
    const float* w2_4 = (const float*)d_in[11];
    const float* b2_4 = (const float*)d_in[12];
    const float* cw2  = (const float*)d_in[13];
    const float* w1_2 = (const float*)d_in[14];
    const float* b1_2 = (const float*)d_in[15];
    const float* w2_2 = (const float*)d_in[16];
    const float* b2_2 = (const float*)d_in[17];
    const float* gw8  = (const float*)d_in[18];
    const float* gb8  = (const float*)d_in[19];
    const float* al8  = (const float*)d_in[20];
    const float* gw4  = (const float*)d_in[21];
    const float* gb4  = (const float*)d_in[22];
    const float* al4  = (const float*)d_in[23];
    const float* gw2  = (const float*)d_in[24];
    const float* gb2  = (const float*)d_in[25];
    const float* al2  = (const float*)d_in[26];
    const float* gw1  = (const float*)d_in[27];
    const float* gb1  = (const float*)d_in[28];
    const float* al1  = (const float*)d_in[29];
    float* out = (float*)d_out;

    float *xn, *tr1, *dst, *h, *o8, *o4, *o2, *means, *w1r, *w2r;
    cudaGetSymbolAddress((void**)&xn,    g_xn);
    cudaGetSymbolAddress((void**)&tr1,   g_trend1);
    cudaGetSymbolAddress((void**)&dst,   g_dstack);
    cudaGetSymbolAddress((void**)&h,     g_h);
    cudaGetSymbolAddress((void**)&o8,    g_out8);
    cudaGetSymbolAddress((void**)&o4,    g_out4);
    cudaGetSymbolAddress((void**)&o2,    g_out2);
    cudaGetSymbolAddress((void**)&means, g_means);
    cudaGetSymbolAddress((void**)&w1r,   g_w1r);
    cudaGetSymbolAddress((void**)&w2r,   g_w2r);

    float* w1r8 = w1r;
    float* w1r4 = w1r + 1024 * 128;
    float* w1r2 = w1r + 1024 * (128 + 256);
    float* w2r8 = w2r;
    float* w2r4 = w2r + 1024 * 1024;
    float* w2r2 = w2r + 2 * 1024 * 1024;

    cudaFuncSetAttribute(gemm_tc_kernel,
                         cudaFuncAttributeMaxDynamicSharedMemorySize, GEMM_SMEM);

    round_tf32_kernel<<<(1024*128 + 255)/256, 256>>>(w1_8, w1r8, 1024*128);
    round_tf32_kernel<<<(1024*256 + 255)/256, 256>>>(w1_4, w1r4, 1024*256);
    round_tf32_kernel<<<(1024*512 + 255)/256, 256>>>(w1_2, w1r2, 1024*512);
    round_tf32_kernel<<<(1024*1024 + 255)/256, 256>>>(w2_8, w2r8, 1024*1024);
    round_tf32_kernel<<<(1024*1024 + 255)/256, 256>>>(w2_4, w2r4, 1024*1024);
    round_tf32_kernel<<<(1024*1024 + 255)/256, 256>>>(w2_2, w2r2, 1024*1024);

    bn_kernel<<<FEAT / 256, 256>>>(x, bng, bnb);
    ema_kernel<<<ROWS / 8, 256>>>(xn, tr1, al1, LEN, 0);

    /* s = 8 */
    {
        const int Ls = 128;
        dwconv_kernel<<<(ROWS * Ls + 255) / 256, 256>>>(xn, cw8, dst, 8, Ls);
        ema_kernel<<<ROWS / 8, 256>>>(dst, dst + (size_t)ROWS * Ls, al8, Ls, 1);
        gemm_tc_kernel<<<dim3(8, 128), 256, GEMM_SMEM>>>(dst, w1r8, h, b1_8, Ls, 1);
        gemm_tc_kernel<<<dim3(8, 128), 256, GEMM_SMEM>>>(h, w2r8, o8, b2_8, 1024, 0);
    }
    /* s = 4 */
    {
        const int Ls = 256;
        dwconv_kernel<<<(ROWS * Ls + 255) / 256, 256>>>(xn, cw4, dst, 4, Ls);
        ema_kernel<<<ROWS / 8, 256>>>(dst, dst + (size_t)ROWS * Ls, al4, Ls, 1);
        gemm_tc_kernel<<<dim3(8, 128), 256, GEMM_SMEM>>>(dst, w1r4, h, b1_4, Ls, 1);
        gemm_tc_kernel<<<dim3(8, 128), 256, GEMM_SMEM>>>(h, w2r4, o4, b2_4, 1024, 0);
    }
    /* s = 2 */
    {
        const int Ls = 512;
        dwconv_kernel<<<(ROWS * Ls + 255) / 256, 256>>>(xn, cw2, dst, 2, Ls);
        ema_kernel<<<ROWS / 8, 256>>>(dst, dst + (size_t)ROWS * Ls, al2, Ls, 1);
        gemm_tc_kernel<<<dim3(8, 128), 256, GEMM_SMEM>>>(dst, w1r2, h, b1_2, Ls, 1);
        gemm_tc_kernel<<<dim3(8, 128), 256, GEMM_SMEM>>>(h, w2r2, o2, b2_2, 1024, 0);
    }

    rowmean_kernel<<<2 * ROWS, 256>>>(o8, means + 0 * 2 * ROWS);
    rowmean_kernel<<<2 * ROWS, 256>>>(o4, means + 1 * 2 * ROWS);
    rowmean_kernel<<<2 * ROWS, 256>>>(o2, means + 2 * 2 * ROWS);
    rowmean_kernel<<<ROWS, 256>>>(xn,  means + 3 * 2 * ROWS);
    rowmean_kernel<<<ROWS, 256>>>(tr1, means + 3 * 2 * ROWS + ROWS);

    gate_kernel<<<BATCH, 128>>>(gw8, gb8, gw4, gb4, gw2, gb2, gw1, gb1);

    combine_kernel<<<(NELEM + 255) / 256, 256>>>(out);
}

// round 6
// speedup vs baseline: 3.2648x; 1.2685x over previous
#include <cuda_runtime.h>
#include <cuda_fp16.h>
#include <math.h>
#include <stdint.h>

#define BATCH 64
#define CH    128
#define LEN   1024
#define ROWS  (BATCH*CH)          /* 8192  */
#define FEAT  (CH*LEN)            /* 131072 */
#define NELEM (BATCH*CH*LEN)      /* 8388608 */

/* ---------------- scratch (static device globals; allocation-free) -------- */
__device__ float  g_xn[NELEM];
__device__ float  g_trend1[NELEM];
__device__ __half g_dstack[2 * ROWS * 512];    /* [down ; trend_ds], half      */
__device__ __half g_h[2 * ROWS * LEN];         /* GEMM1 output (gelu'd, half)  */
__device__ float  g_out8[2 * ROWS * LEN];
__device__ float  g_out4[2 * ROWS * LEN];
__device__ float  g_out2[2 * ROWS * LEN];
__device__ float  g_means[4 * 2 * ROWS];
__device__ float  g_gates[BATCH * 4];
__device__ __half g_w1h[1024 * (512 + 256 + 128)];
__device__ __half g_w2h[3 * 1024 * 1024];

/* ---------------- fp32 -> fp16 weight conversion --------------------------- */
__global__ void round_h_kernel(const float* __restrict__ src,
                               __half* __restrict__ dst, int n) {
    int i = blockIdx.x * blockDim.x + threadIdx.x;
    if (i < n) dst[i] = __float2half_rn(src[i]);
}

/* ---------------- BatchNorm over batch axis ------------------------------- */
__global__ void bn_kernel(const float* __restrict__ x,
                          const float* __restrict__ gam,
                          const float* __restrict__ bet) {
    int f = blockIdx.x * blockDim.x + threadIdx.x;
    if (f >= FEAT) return;
    float v[BATCH];
    float s = 0.f;
#pragma unroll
    for (int b = 0; b < BATCH; b++) { v[b] = x[(size_t)b * FEAT + f]; s += v[b]; }
    float mu = s * (1.f / BATCH);
    float q = 0.f;
#pragma unroll
    for (int b = 0; b < BATCH; b++) { float d = v[b] - mu; q += d * d; }
    float inv = rsqrtf(q * (1.f / BATCH) + 1e-5f);
    float gg = gam[f] * inv, bb = bet[f];
#pragma unroll
    for (int b = 0; b < BATCH; b++)
        g_xn[(size_t)b * FEAT + f] = (v[b] - mu) * gg + bb;
}

/* ---------------- depthwise strided conv (half output) -------------------- */
__global__ void dwconv_kernel(const float* __restrict__ xn,
                              const float* __restrict__ cw,
                              __half* __restrict__ out, int s, int Ls) {
    int idx = blockIdx.x * blockDim.x + threadIdx.x;
    if (idx >= ROWS * Ls) return;
    int t = idx % Ls, row = idx / Ls, c = row % CH;
    const float* xr = xn + (size_t)row * LEN;
    const float* w  = cw + c * 2 * s;
    int base = t * s - s / 2;
    float acc = 0.f;
    for (int k = 0; k < 2 * s; k++) {
        int p = base + k;
        if (p >= 0 && p < LEN) acc = fmaf(xr[p], w[k], acc);
    }
    out[idx] = __float2half_rn(acc);
}

/* ---------------- EMA (reference cumsum formulation), typed IO ------------- */
template <typename TI, typename TO>
__global__ void ema_kernel(const TI* __restrict__ src,
                           TO* __restrict__ dst,
                           const float* __restrict__ al, int Ls) {
    int warp = (blockIdx.x * blockDim.x + threadIdx.x) >> 5;
    int lane = threadIdx.x & 31;
    if (warp >= ROWS) return;
    int c = warp % CH;
    float a  = 1.f / (1.f + expf(-al[c]));
    float om = 1.f - a;
    float l2 = log2f(om);
    const TI* x = src + (size_t)warp * Ls;
    TO* y       = dst + (size_t)warp * Ls;
    float cnum = 0.f, cden = 0.f;
    for (int j0 = 0; j0 < Ls; j0 += 32) {
        int j = j0 + lane;
        float p = (float)(Ls - 1 - j);
        float base = exp2f(p * l2);
        float wn = (j == 0) ? base : base * a;
        float n = (float)x[j] * wn;
        float d = base;
#pragma unroll
        for (int o = 1; o < 32; o <<= 1) {
            float nn = __shfl_up_sync(0xffffffffu, n, o);
            float dd = __shfl_up_sync(0xffffffffu, d, o);
            if (lane >= o) { n += nn; d += dd; }
        }
        n += cnum; d += cden;
        y[j] = (TO)(n / fmaxf(d, 1e-12f));
        cnum = __shfl_sync(0xffffffffu, n, 31);
        cden = __shfl_sync(0xffffffffu, d, 31);
    }
}

/* ============ fp16 tensor-core GEMM  C[M,1024] = A[M,K]*B[N,K]^T =========== */
/* BM=BN=128, BK=32 halves, 2-stage cp.async double buffer.                    */
/* smem [row][k] pitch 40 halves (20 words) -> conflict-free fragment LDS.     */

#define PITCH_H 40
#define PITCH_W 20                    /* pitch in 32-bit words */
#define BKH 32
#define STAGE_H (128 * PITCH_H)       /* halves per matrix per stage */

__device__ __forceinline__ uint32_t smem_u32(const void* p) {
    uint32_t a;
    asm("{.reg .u64 t; cvta.to.shared.u64 t, %1; cvt.u32.u64 %0, t;}"
        : "=r"(a) : "l"(p));
    return a;
}
__device__ __forceinline__ void cp_async16(uint32_t saddr, const void* g) {
    asm volatile("cp.async.cg.shared.global [%0], [%1], 16;"
                 :: "r"(saddr), "l"(g));
}
__device__ __forceinline__ void mma_f16(float* d,
                                        const uint32_t* a, const uint32_t* b,
                                        const float* c) {
    asm volatile(
        "mma.sync.aligned.m16n8k16.row.col.f32.f16.f16.f32 "
        "{%0,%1,%2,%3}, {%4,%5,%6,%7}, {%8,%9}, {%10,%11,%12,%13};"
        : "=f"(d[0]), "=f"(d[1]), "=f"(d[2]), "=f"(d[3])
        : "r"(a[0]), "r"(a[1]), "r"(a[2]), "r"(a[3]),
          "r"(b[0]), "r"(b[1]),
          "f"(c[0]), "f"(c[1]), "f"(c[2]), "f"(c[3]));
}

__device__ __forceinline__ float gelu_exact(float v) {
    return 0.5f * v * (1.f + erff(v * 0.70710678118654752f));
}

__global__ void __launch_bounds__(256, 2)
gemm_h_kernel(const __half* __restrict__ A, const __half* __restrict__ B,
              void* __restrict__ Cout, const float* __restrict__ bias,
              int K, int act) {
    __shared__ __half As[2][STAGE_H];
    __shared__ __half Bs[2][STAGE_H];
    const int tid  = threadIdx.x;
    const int wid  = tid >> 5;
    const int lane = tid & 31;
    const int g    = lane >> 2;
    const int tg   = lane & 3;
    const int wm   = (wid >> 1) * 32;
    const int wn   = (wid & 1) * 64;
    const int m0 = blockIdx.y * 128, n0 = blockIdx.x * 128;

    /* loader: thread -> one row (A if tid<128 else B), 4x16B per stage */
    const int mat = tid >> 7, row = tid & 127;
    const __half* src = mat ? (B + (size_t)(n0 + row) * K)
                            : (A + (size_t)(m0 + row) * K);
    const uint32_t sbase = (mat ? smem_u32(&Bs[0][0]) : smem_u32(&As[0][0]))
                           + row * (PITCH_H * 2);
    const uint32_t stbytes = STAGE_H * 2;

    float acc[2][8][4];
#pragma unroll
    for (int i = 0; i < 2; i++)
#pragma unroll
        for (int j = 0; j < 8; j++)
#pragma unroll
            for (int q = 0; q < 4; q++) acc[i][j][q] = 0.f;

    const int niter = K / BKH;

    /* prologue: stage 0 */
#pragma unroll
    for (int c = 0; c < 4; c++)
        cp_async16(sbase + c * 16, src + c * 8);
    asm volatile("cp.async.commit_group;");

    for (int i = 0; i < niter; i++) {
        if (i + 1 < niter) {
            const __half* gsrc = src + (i + 1) * BKH;
            uint32_t d = ((i + 1) & 1) * stbytes;
#pragma unroll
            for (int c = 0; c < 4; c++)
                cp_async16(sbase + d + c * 16, gsrc + c * 8);
            asm volatile("cp.async.commit_group;");
            asm volatile("cp.async.wait_group 1;");
        } else {
            asm volatile("cp.async.wait_group 0;");
        }
        __syncthreads();

        const uint32_t* as = (const uint32_t*)As[i & 1];
        const uint32_t* bs = (const uint32_t*)Bs[i & 1];
#pragma unroll
        for (int kk = 0; kk < 2; kk++) {          /* two K=16 sub-steps */
            const int kw = kk * 8 + tg;           /* word offset in row */
            uint32_t af[2][4], bf[8][2];
#pragma unroll
            for (int mt = 0; mt < 2; mt++) {
                int mb = (wm + mt * 16 + g) * PITCH_W + kw;
                af[mt][0] = as[mb];
                af[mt][1] = as[mb + 8 * PITCH_W];
                af[mt][2] = as[mb + 4];
                af[mt][3] = as[mb + 8 * PITCH_W + 4];
            }
#pragma unroll
            for (int nt = 0; nt < 8; nt++) {
                int nb = (wn + nt * 8 + g) * PITCH_W + kw;
                bf[nt][0] = bs[nb];
                bf[nt][1] = bs[nb + 4];
            }
#pragma unroll
            for (int mt = 0; mt < 2; mt++)
#pragma unroll
                for (int nt = 0; nt < 8; nt++)
                    mma_f16(acc[mt][nt], af[mt], bf[nt], acc[mt][nt]);
        }
        __syncthreads();
    }

    /* epilogue: bias; act -> gelu + half store (feeds GEMM2), else fp32 */
#pragma unroll
    for (int mt = 0; mt < 2; mt++) {
        int r0 = m0 + wm + mt * 16 + g;
#pragma unroll
        for (int nt = 0; nt < 8; nt++) {
            int c0 = n0 + wn + nt * 8 + 2 * tg;
            float b0 = bias[c0], b1 = bias[c0 + 1];
            float v0 = acc[mt][nt][0] + b0;
            float v1 = acc[mt][nt][1] + b1;
            float v2 = acc[mt][nt][2] + b0;
            float v3 = acc[mt][nt][3] + b1;
            if (act) {
                __half* C = (__half*)Cout;
                __half2 p01 = __floats2half2_rn(gelu_exact(v0), gelu_exact(v1));
                __half2 p23 = __floats2half2_rn(gelu_exact(v2), gelu_exact(v3));
                *(__half2*)(C + (size_t)r0 * 1024 + c0)       = p01;
                *(__half2*)(C + (size_t)(r0 + 8) * 1024 + c0) = p23;
            } else {
                float* C = (float*)Cout;
                *(float2*)(C + (size_t)r0 * 1024 + c0)       = make_float2(v0, v1);
                *(float2*)(C + (size_t)(r0 + 8) * 1024 + c0) = make_float2(v2, v3);
            }
        }
    }
}

/* ---------------- per-row mean over L -------------------------------------- */
__global__ void rowmean_kernel(const float* __restrict__ src,
                               float* __restrict__ dst) {
    int row = blockIdx.x;
    const float* p = src + (size_t)row * LEN;
    float s = 0.f;
    for (int i = threadIdx.x; i < LEN; i += 256) s += p[i];
    __shared__ float sm[256];
    sm[threadIdx.x] = s; __syncthreads();
    for (int o = 128; o > 0; o >>= 1) {
        if (threadIdx.x < o) sm[threadIdx.x] += sm[threadIdx.x + o];
        __syncthreads();
    }
    if (threadIdx.x == 0) dst[row] = sm[0] * (1.f / LEN);
}

/* ---------------- gates ----------------------------------------------------- */
__global__ void gate_kernel(const float* __restrict__ gw8, const float* __restrict__ gb8,
                            const float* __restrict__ gw4, const float* __restrict__ gb4,
                            const float* __restrict__ gw2, const float* __restrict__ gb2,
                            const float* __restrict__ gw1, const float* __restrict__ gb1) {
    int b = blockIdx.x;
    int c = threadIdx.x;
    __shared__ float red[4][128];
    const float* gws[4] = {gw8, gw4, gw2, gw1};
    for (int s = 0; s < 4; s++) {
        float um = g_means[(s * 2 + 0) * ROWS + b * CH + c];
        float tm = g_means[(s * 2 + 1) * ROWS + b * CH + c];
        red[s][c] = (um - tm) * gws[s][c];
    }
    __syncthreads();
    for (int o = 64; o > 0; o >>= 1) {
        if (c < o) {
            for (int s = 0; s < 4; s++) red[s][c] += red[s][c + o];
        }
        __syncthreads();
    }
    if (c == 0) {
        float gbv[4] = {gb8[0], gb4[0], gb2[0], gb1[0]};
        float gv[4], tot = 0.f;
        for (int s = 0; s < 4; s++) {
            gv[s] = 1.f / (1.f + expf(-(red[s][0] + gbv[s])));
            tot += gv[s];
        }
        for (int s = 0; s < 4; s++) g_gates[b * 4 + s] = gv[s] / (tot + 1e-6f);
    }
}

/* ---------------- final weighted combine; out = [season ; trend] ----------- */
__global__ void combine_kernel(float* __restrict__ out) {
    size_t idx = blockIdx.x * (size_t)blockDim.x + threadIdx.x;
    if (idx >= NELEM) return;
    int b = (int)(idx >> 10) / CH;
    const float* G = g_gates + b * 4;
    float g0 = G[0], g1 = G[1], g2 = G[2], g3 = G[3];
    float u8 = g_out8[idx], t8 = g_out8[idx + (size_t)NELEM];
    float u4 = g_out4[idx], t4 = g_out4[idx + (size_t)NELEM];
    float u2 = g_out2[idx], t2 = g_out2[idx + (size_t)NELEM];
    float u1 = g_xn[idx],   t1 = g_trend1[idx];
    float trend  = g0 * t8 + g1 * t4 + g2 * t2 + g3 * t1;
    float season = g0 * (u8 - t8) + g1 * (u4 - t4) + g2 * (u2 - t2) + g3 * (u1 - t1);
    out[idx] = season;
    out[(size_t)NELEM + idx] = trend;
}

/* ---------------- host orchestration -------------------------------------- */
extern "C" void kernel_launch(void* const* d_in, const int* in_sizes, int n_in,
                              void* d_out, int out_size) {
    const float* x    = (const float*)d_in[0];
    const float* bng  = (const float*)d_in[1];
    const float* bnb  = (const float*)d_in[2];
    const float* cw8  = (const float*)d_in[3];
    const float* w1_8 = (const float*)d_in[4];
    const float* b1_8 = (const float*)d_in[5];
    const float* w2_8 = (const float*)d_in[6];
    const float* b2_8 = (const float*)d_in[7];
    const float* cw4  = (const float*)d_in[8];
    const float* w1_4 = (const float*)d_in[9];
    const float* b1_4 = (const float*)d_in[10];
    const float* w2_4 = (const float*)d_in[11];
    const float* b2_4 = (const float*)d_in[12];
    const float* cw2  = (const float*)d_in[13];
    const float* w1_2 = (const float*)d_in[14];
    const float* b1_2 = (const float*)d_in[15];
    const float* w2_2 = (const float*)d_in[16];
    const float* b2_2 = (const float*)d_in[17];
    const float* gw8  = (const float*)d_in[18];
    const float* gb8  = (const float*)d_in[19];
    const float* al8  = (const float*)d_in[20];
    const float* gw4  = (const float*)d_in[21];
    const float* gb4  = (const float*)d_in[22];
    const float* al4  = (const float*)d_in[23];
    const float* gw2  = (const float*)d_in[24];
    const float* gb2  = (const float*)d_in[25];
    const float* al2  = (const float*)d_in[26];
    const float* gw1  = (const float*)d_in[27];
    const float* gb1  = (const float*)d_in[28];
    const float* al1  = (const float*)d_in[29];
    float* out = (float*)d_out;

    float *xn, *tr1, *o8, *o4, *o2, *means;
    __half *dst, *h, *w1h, *w2h;
    cudaGetSymbolAddress((void**)&xn,    g_xn);
    cudaGetSymbolAddress((void**)&tr1,   g_trend1);
    cudaGetSymbolAddress((void**)&dst,   g_dstack);
    cudaGetSymbolAddress((void**)&h,     g_h);
    cudaGetSymbolAddress((void**)&o8,    g_out8);
    cudaGetSymbolAddress((void**)&o4,    g_out4);
    cudaGetSymbolAddress((void**)&o2,    g_out2);
    cudaGetSymbolAddress((void**)&means, g_means);
    cudaGetSymbolAddress((void**)&w1h,   g_w1h);
    cudaGetSymbolAddress((void**)&w2h,   g_w2h);

    __half* w1h8 = w1h;
    __half* w1h4 = w1h + 1024 * 128;
    __half* w1h2 = w1h + 1024 * (128 + 256);
    __half* w2h8 = w2h;
    __half* w2h4 = w2h + 1024 * 1024;
    __half* w2h2 = w2h + 2 * 1024 * 1024;

    round_h_kernel<<<(1024*128 + 255)/256, 256>>>(w1_8, w1h8, 1024*128);
    round_h_kernel<<<(1024*256 + 255)/256, 256>>>(w1_4, w1h4, 1024*256);
    round_h_kernel<<<(1024*512 + 255)/256, 256>>>(w1_2, w1h2, 1024*512);
    round_h_kernel<<<(1024*1024 + 255)/256, 256>>>(w2_8, w2h8, 1024*1024);
    round_h_kernel<<<(1024*1024 + 255)/256, 256>>>(w2_4, w2h4, 1024*1024);
    round_h_kernel<<<(1024*1024 + 255)/256, 256>>>(w2_2, w2h2, 1024*1024);

    bn_kernel<<<FEAT / 256, 256>>>(x, bng, bnb);
    ema_kernel<float, float><<<ROWS / 8, 256>>>(xn, tr1, al1, LEN);

    /* s = 8 */
    {
        const int Ls = 128;
        dwconv_kernel<<<(ROWS * Ls + 255) / 256, 256>>>(xn, cw8, dst, 8, Ls);
        ema_kernel<__half, __half><<<ROWS / 8, 256>>>(dst, dst + (size_t)ROWS * Ls, al8, Ls);
        gemm_h_kernel<<<dim3(8, 128), 256>>>(dst, w1h8, h, b1_8, Ls, 1);
        gemm_h_kernel<<<dim3(8, 128), 256>>>(h, w2h8, o8, b2_8, 1024, 0);
    }
    /* s = 4 */
    {
        const int Ls = 256;
        dwconv_kernel<<<(ROWS * Ls + 255) / 256, 256>>>(xn, cw4, dst, 4, Ls);
        ema_kernel<__half, __half><<<ROWS / 8, 256>>>(dst, dst + (size_t)ROWS * Ls, al4, Ls);
        gemm_h_kernel<<<dim3(8, 128), 256>>>(dst, w1h4, h, b1_4, Ls, 1);
        gemm_h_kernel<<<dim3(8, 128), 256>>>(h, w2h4, o4, b2_4, 1024, 0);
    }
    /* s = 2 */
    {
        const int Ls = 512;
        dwconv_kernel<<<(ROWS * Ls + 255) / 256, 256>>>(xn, cw2, dst, 2, Ls);
        ema_kernel<__half, __half><<<ROWS / 8, 256>>>(dst, dst + (size_t)ROWS * Ls, al2, Ls);
        gemm_h_kernel<<<dim3(8, 128), 256>>>(dst, w1h2, h, b1_2, Ls, 1);
        gemm_h_kernel<<<dim3(8, 128), 256>>>(h, w2h2, o2, b2_2, 1024, 0);
    }

    rowmean_kernel<<<2 * ROWS, 256>>>(o8, means + 0 * 2 * ROWS);
    rowmean_kernel<<<2 * ROWS, 256>>>(o4, means + 1 * 2 * ROWS);
    rowmean_kernel<<<2 * ROWS, 256>>>(o2, means + 2 * 2 * ROWS);
    rowmean_kernel<<<ROWS, 256>>>(xn,  means + 3 * 2 * ROWS);
    rowmean_kernel<<<ROWS, 256>>>(tr1, means + 3 * 2 * ROWS + ROWS);

    gate_kernel<<<BATCH, 128>>>(gw8, gb8, gw4, gb4, gw2, gb2, gw1, gb1);

    combine_kernel<<<(NELEM + 255) / 256, 256>>>(out);
}

// round 7
// speedup vs baseline: 3.7432x; 1.1465x over previous
#include <cuda_runtime.h>
#include <cuda_fp16.h>
#include <math.h>
#include <stdint.h>

#define BATCH 64
#define CH    128
#define LEN   1024
#define ROWS  (BATCH*CH)          /* 8192  */
#define FEAT  (CH*LEN)            /* 131072 */
#define NELEM (BATCH*CH*LEN)      /* 8388608 */

/* ---------------- scratch (static device globals; allocation-free) -------- */
__device__ float  g_xn[NELEM];
__device__ float  g_trend1[NELEM];
__device__ __half g_dstack[2 * ROWS * 512];
__device__ __half g_h[2 * ROWS * LEN];
__device__ float  g_out8[2 * ROWS * LEN];
__device__ float  g_out4[2 * ROWS * LEN];
__device__ float  g_out2[2 * ROWS * LEN];
__device__ float  g_means[4 * 2 * ROWS];       /* row SUMS (÷L in gate)      */
__device__ float  g_gates[BATCH * 4];
__device__ __half g_w1h[1024 * (512 + 256 + 128)];
__device__ __half g_w2h[3 * 1024 * 1024];

/* ---------------- prep: convert all weights to half + zero mean-sums ------- */
#define NW_TOTAL (1024*(512+256+128) + 3*1024*1024)   /* 4063232 */
__global__ void prep_kernel(const float* __restrict__ w18, const float* __restrict__ w14,
                            const float* __restrict__ w12, const float* __restrict__ w28,
                            const float* __restrict__ w24, const float* __restrict__ w22) {
    int i = blockIdx.x * blockDim.x + threadIdx.x;
    if (i < 6 * ROWS) g_means[i] = 0.f;        /* sums for scales 8,4,2 */
    if (i >= NW_TOTAL) return;
    float v;
    int j = i;
    __half* dst;
    if (j < 131072)            { v = w18[j];            dst = g_w1h + j; }
    else if (j < 393216)       { v = w14[j - 131072];   dst = g_w1h + j; }
    else if (j < 917504)       { v = w12[j - 393216];   dst = g_w1h + j; }
    else if (j < 1966080)      { v = w28[j - 917504];   dst = g_w2h + (j - 917504); }
    else if (j < 3014656)      { v = w24[j - 1966080];  dst = g_w2h + (j - 917504); }
    else                       { v = w22[j - 3014656];  dst = g_w2h + (j - 917504); }
    *dst = __float2half_rn(v);
}

/* ---------------- BatchNorm over batch axis ------------------------------- */
__global__ void bn_kernel(const float* __restrict__ x,
                          const float* __restrict__ gam,
                          const float* __restrict__ bet) {
    int f = blockIdx.x * blockDim.x + threadIdx.x;
    if (f >= FEAT) return;
    float v[BATCH];
    float s = 0.f;
#pragma unroll
    for (int b = 0; b < BATCH; b++) { v[b] = x[(size_t)b * FEAT + f]; s += v[b]; }
    float mu = s * (1.f / BATCH);
    float q = 0.f;
#pragma unroll
    for (int b = 0; b < BATCH; b++) { float d = v[b] - mu; q += d * d; }
    float inv = rsqrtf(q * (1.f / BATCH) + 1e-5f);
    float gg = gam[f] * inv, bb = bet[f];
#pragma unroll
    for (int b = 0; b < BATCH; b++)
        g_xn[(size_t)b * FEAT + f] = (v[b] - mu) * gg + bb;
}

/* ---------------- depthwise strided conv (half output) -------------------- */
__global__ void dwconv_kernel(const float* __restrict__ xn,
                              const float* __restrict__ cw,
                              __half* __restrict__ out, int s, int Ls) {
    int idx = blockIdx.x * blockDim.x + threadIdx.x;
    if (idx >= ROWS * Ls) return;
    int t = idx % Ls, row = idx / Ls, c = row % CH;
    const float* xr = xn + (size_t)row * LEN;
    const float* w  = cw + c * 2 * s;
    int base = t * s - s / 2;
    float acc = 0.f;
    for (int k = 0; k < 2 * s; k++) {
        int p = base + k;
        if (p >= 0 && p < LEN) acc = fmaf(xr[p], w[k], acc);
    }
    out[idx] = __float2half_rn(acc);
}

/* ---------------- EMA (reference cumsum formulation), typed IO ------------- */
/* sumx/sumy non-null (s=1 call): also emit per-row sums of input & output.   */
template <typename TI, typename TO>
__global__ void ema_kernel(const TI* __restrict__ src,
                           TO* __restrict__ dst,
                           const float* __restrict__ al, int Ls,
                           float* __restrict__ sumx, float* __restrict__ sumy) {
    int warp = (blockIdx.x * blockDim.x + threadIdx.x) >> 5;
    int lane = threadIdx.x & 31;
    if (warp >= ROWS) return;
    int c = warp % CH;
    float a  = 1.f / (1.f + expf(-al[c]));
    float om = 1.f - a;
    float l2 = log2f(om);
    const TI* x = src + (size_t)warp * Ls;
    TO* y       = dst + (size_t)warp * Ls;
    float cnum = 0.f, cden = 0.f;
    float sx = 0.f, sy = 0.f;
    for (int j0 = 0; j0 < Ls; j0 += 32) {
        int j = j0 + lane;
        float p = (float)(Ls - 1 - j);
        float base = exp2f(p * l2);
        float wn = (j == 0) ? base : base * a;
        float xv = (float)x[j];
        float n = xv * wn;
        float d = base;
#pragma unroll
        for (int o = 1; o < 32; o <<= 1) {
            float nn = __shfl_up_sync(0xffffffffu, n, o);
            float dd = __shfl_up_sync(0xffffffffu, d, o);
            if (lane >= o) { n += nn; d += dd; }
        }
        n += cnum; d += cden;
        float yv = n / fmaxf(d, 1e-12f);
        y[j] = (TO)yv;
        sx += xv; sy += yv;
        cnum = __shfl_sync(0xffffffffu, n, 31);
        cden = __shfl_sync(0xffffffffu, d, 31);
    }
    if (sumx) {
#pragma unroll
        for (int o = 16; o > 0; o >>= 1) {
            sx += __shfl_xor_sync(0xffffffffu, sx, o);
            sy += __shfl_xor_sync(0xffffffffu, sy, o);
        }
        if (lane == 0) { sumx[warp] = sx; sumy[warp] = sy; }
    }
}

/* ============ fp16 tensor-core GEMM  C[M,1024] = A[M,K]*B[N,K]^T =========== */
/* BM=BN=128, BK=64 halves, 2-stage cp.async, ldmatrix fragment loads.         */
/* smem [row][k] pitch 72 halves (144B) -> conflict-free LDSM phases.          */

#define PITCH_H 72
#define PITCH_B 144
#define BKH 64
#define MAT_STAGE_B 18432             /* 128 * 144 */
#define B_OFF 36864                   /* A stages [0,36864), B after */
#define GEMM_SMEM_B 73728

__device__ __forceinline__ uint32_t smem_u32(const void* p) {
    uint32_t a;
    asm("{.reg .u64 t; cvta.to.shared.u64 t, %1; cvt.u32.u64 %0, t;}"
        : "=r"(a) : "l"(p));
    return a;
}
__device__ __forceinline__ void cp_async16(uint32_t saddr, const void* g) {
    asm volatile("cp.async.cg.shared.global [%0], [%1], 16;"
                 :: "r"(saddr), "l"(g));
}
#define LDSM4(r0, r1, r2, r3, addr) \
    asm volatile("ldmatrix.sync.aligned.m8n8.x4.shared.b16 {%0,%1,%2,%3}, [%4];" \
                 : "=r"(r0), "=r"(r1), "=r"(r2), "=r"(r3) : "r"(addr))

__device__ __forceinline__ void mma_f16(float* d,
                                        const uint32_t* a, const uint32_t* b,
                                        const float* c) {
    asm volatile(
        "mma.sync.aligned.m16n8k16.row.col.f32.f16.f16.f32 "
        "{%0,%1,%2,%3}, {%4,%5,%6,%7}, {%8,%9}, {%10,%11,%12,%13};"
        : "=f"(d[0]), "=f"(d[1]), "=f"(d[2]), "=f"(d[3])
        : "r"(a[0]), "r"(a[1]), "r"(a[2]), "r"(a[3]),
          "r"(b[0]), "r"(b[1]),
          "f"(c[0]), "f"(c[1]), "f"(c[2]), "f"(c[3]));
}

__device__ __forceinline__ float gelu_exact(float v) {
    return 0.5f * v * (1.f + erff(v * 0.70710678118654752f));
}

__global__ void __launch_bounds__(256, 2)
gemm_h_kernel(const __half* __restrict__ A, const __half* __restrict__ B,
              void* __restrict__ Cout, const float* __restrict__ bias,
              int K, int act, float* __restrict__ sums) {
    extern __shared__ char smem[];
    const uint32_t sb = smem_u32(smem);
    const int tid  = threadIdx.x;
    const int wid  = tid >> 5;
    const int lane = tid & 31;
    const int g    = lane >> 2;
    const int tg   = lane & 3;
    const int wm   = (wid >> 1) * 32;
    const int wn   = (wid & 1) * 64;
    const int m0 = blockIdx.y * 128, n0 = blockIdx.x * 128;

    /* loader: thread -> one row's 64 halves (128B = 8 x 16B) per stage */
    const int mat = tid >> 7, row = tid & 127;
    const __half* src = mat ? (B + (size_t)(n0 + row) * K)
                            : (A + (size_t)(m0 + row) * K);
    const uint32_t sldbase = sb + mat * B_OFF + row * PITCH_B;

    /* ldmatrix per-lane addressing */
    const int lr16 = lane & 15;
    const int lhi  = (lane >> 4) << 3;          /* +8 halves for lanes 16-31 */
    const uint32_t a_ab = sb + ((wm + lr16) * PITCH_H + lhi) * 2;
    const uint32_t b_ab = sb + B_OFF + ((wn + lr16) * PITCH_H + lhi) * 2;

    float acc[2][8][4];
#pragma unroll
    for (int i = 0; i < 2; i++)
#pragma unroll
        for (int j = 0; j < 8; j++)
#pragma unroll
            for (int q = 0; q < 4; q++) acc[i][j][q] = 0.f;

    const int niter = K / BKH;

    /* prologue: stage 0 */
#pragma unroll
    for (int c = 0; c < 8; c++)
        cp_async16(sldbase + c * 16, src + c * 8);
    asm volatile("cp.async.commit_group;");

    for (int i = 0; i < niter; i++) {
        if (i + 1 < niter) {
            const __half* gsrc = src + (i + 1) * BKH;
            uint32_t d = ((i + 1) & 1) * MAT_STAGE_B;
#pragma unroll
            for (int c = 0; c < 8; c++)
                cp_async16(sldbase + d + c * 16, gsrc + c * 8);
            asm volatile("cp.async.commit_group;");
            asm volatile("cp.async.wait_group 1;");
        } else {
            asm volatile("cp.async.wait_group 0;");
        }
        __syncthreads();

        const uint32_t stg = (i & 1) * MAT_STAGE_B;
        const uint32_t aa = a_ab + stg;
        const uint32_t bb = b_ab + stg;
#pragma unroll
        for (int kk = 0; kk < 4; kk++) {          /* four K=16 sub-steps */
            const uint32_t kb = kk * 32;          /* 16 halves = 32B */
            uint32_t af[2][4], bf[8][2];
            LDSM4(af[0][0], af[0][1], af[0][2], af[0][3], aa + kb);
            LDSM4(af[1][0], af[1][1], af[1][2], af[1][3],
                  aa + kb + 16 * PITCH_B);
#pragma unroll
            for (int p = 0; p < 4; p++) {
                uint32_t q0, q1, q2, q3;
                LDSM4(q0, q1, q2, q3, bb + kb + p * 16 * PITCH_B);
                bf[2 * p][0] = q0; bf[2 * p + 1][0] = q1;
                bf[2 * p][1] = q2; bf[2 * p + 1][1] = q3;
            }
#pragma unroll
            for (int mt = 0; mt < 2; mt++)
#pragma unroll
                for (int nt = 0; nt < 8; nt++)
                    mma_f16(acc[mt][nt], af[mt], bf[nt], acc[mt][nt]);
        }
        __syncthreads();
    }

    /* epilogue */
#pragma unroll
    for (int mt = 0; mt < 2; mt++) {
        int r0 = m0 + wm + mt * 16 + g;
        float s0 = 0.f, s1 = 0.f;
#pragma unroll
        for (int nt = 0; nt < 8; nt++) {
            int c0 = n0 + wn + nt * 8 + 2 * tg;
            float b0 = bias[c0], b1 = bias[c0 + 1];
            float v0 = acc[mt][nt][0] + b0;
            float v1 = acc[mt][nt][1] + b1;
            float v2 = acc[mt][nt][2] + b0;
            float v3 = acc[mt][nt][3] + b1;
            if (act) {
                __half* C = (__half*)Cout;
                __half2 p01 = __floats2half2_rn(gelu_exact(v0), gelu_exact(v1));
                __half2 p23 = __floats2half2_rn(gelu_exact(v2), gelu_exact(v3));
                *(__half2*)(C + (size_t)r0 * 1024 + c0)       = p01;
                *(__half2*)(C + (size_t)(r0 + 8) * 1024 + c0) = p23;
            } else {
                float* C = (float*)Cout;
                *(float2*)(C + (size_t)r0 * 1024 + c0)       = make_float2(v0, v1);
                *(float2*)(C + (size_t)(r0 + 8) * 1024 + c0) = make_float2(v2, v3);
                s0 += v0 + v1;
                s1 += v2 + v3;
            }
        }
        if (sums) {                    /* fused row-sum for gating */
            s0 += __shfl_xor_sync(0xffffffffu, s0, 1);
            s0 += __shfl_xor_sync(0xffffffffu, s0, 2);
            s1 += __shfl_xor_sync(0xffffffffu, s1, 1);
            s1 += __shfl_xor_sync(0xffffffffu, s1, 2);
            if (tg == 0) {
                atomicAdd(&sums[r0], s0);
                atomicAdd(&sums[r0 + 8], s1);
            }
        }
    }
}

/* ---------------- gates (means = sums / L) ---------------------------------- */
__global__ void gate_kernel(const float* __restrict__ gw8, const float* __restrict__ gb8,
                            const float* __restrict__ gw4, const float* __restrict__ gb4,
                            const float* __restrict__ gw2, const float* __restrict__ gb2,
                            const float* __restrict__ gw1, const float* __restrict__ gb1) {
    int b = blockIdx.x;
    int c = threadIdx.x;
    __shared__ float red[4][128];
    const float* gws[4] = {gw8, gw4, gw2, gw1};
    const float invL = 1.f / LEN;
    for (int s = 0; s < 4; s++) {
        float su = g_means[(s * 2 + 0) * ROWS + b * CH + c];
        float st = g_means[(s * 2 + 1) * ROWS + b * CH + c];
        red[s][c] = (su - st) * invL * gws[s][c];
    }
    __syncthreads();
    for (int o = 64; o > 0; o >>= 1) {
        if (c < o) {
            for (int s = 0; s < 4; s++) red[s][c] += red[s][c + o];
        }
        __syncthreads();
    }
    if (c == 0) {
        float gbv[4] = {gb8[0], gb4[0], gb2[0], gb1[0]};
        float gv[4], tot = 0.f;
        for (int s = 0; s < 4; s++) {
            gv[s] = 1.f / (1.f + expf(-(red[s][0] + gbv[s])));
            tot += gv[s];
        }
        for (int s = 0; s < 4; s++) g_gates[b * 4 + s] = gv[s] / (tot + 1e-6f);
    }
}

/* ---------------- final weighted combine; out = [season ; trend] ----------- */
__global__ void combine_kernel(float* __restrict__ out) {
    size_t idx = blockIdx.x * (size_t)blockDim.x + threadIdx.x;
    if (idx >= NELEM) return;
    int b = (int)(idx >> 10) / CH;
    const float* G = g_gates + b * 4;
    float g0 = G[0], g1 = G[1], g2 = G[2], g3 = G[3];
    float u8 = g_out8[idx], t8 = g_out8[idx + (size_t)NELEM];
    float u4 = g_out4[idx], t4 = g_out4[idx + (size_t)NELEM];
    float u2 = g_out2[idx], t2 = g_out2[idx + (size_t)NELEM];
    float u1 = g_xn[idx],   t1 = g_trend1[idx];
    float trend  = g0 * t8 + g1 * t4 + g2 * t2 + g3 * t1;
    float season = g0 * (u8 - t8) + g1 * (u4 - t4) + g2 * (u2 - t2) + g3 * (u1 - t1);
    out[idx] = season;
    out[(size_t)NELEM + idx] = trend;
}

/* ---------------- host orchestration -------------------------------------- */
extern "C" void kernel_launch(void* const* d_in, const int* in_sizes, int n_in,
                              void* d_out, int out_size) {
    const float* x    = (const float*)d_in[0];
    const float* bng  = (const float*)d_in[1];
    const float* bnb  = (const float*)d_in[2];
    const float* cw8  = (const float*)d_in[3];
    const float* w1_8 = (const float*)d_in[4];
    const float* b1_8 = (const float*)d_in[5];
    const float* w2_8 = (const float*)d_in[6];
    const float* b2_8 = (const float*)d_in[7];
    const float* cw4  = (const float*)d_in[8];
    const float* w1_4 = (const float*)d_in[9];
    const float* b1_4 = (const float*)d_in[10];
    const float* w2_4 = (const float*)d_in[11];
    const float* b2_4 = (const float*)d_in[12];
    const float* cw2  = (const float*)d_in[13];
    const float* w1_2 = (const float*)d_in[14];
    const float* b1_2 = (const float*)d_in[15];
    const float* w2_2 = (const float*)d_in[16];
    const float* b2_2 = (const float*)d_in[17];
    const float* gw8  = (const float*)d_in[18];
    const float* gb8  = (const float*)d_in[19];
    const float* al8  = (const float*)d_in[20];
    const float* gw4  = (const float*)d_in[21];
    const float* gb4  = (const float*)d_in[22];
    const float* al4  = (const float*)d_in[23];
    const float* gw2  = (const float*)d_in[24];
    const float* gb2  = (const float*)d_in[25];
    const float* al2  = (const float*)d_in[26];
    const float* gw1  = (const float*)d_in[27];
    const float* gb1  = (const float*)d_in[28];
    const float* al1  = (const float*)d_in[29];
    float* out = (float*)d_out;

    float *xn, *tr1, *o8, *o4, *o2, *means;
    __half *dst, *h, *w1h, *w2h;
    cudaGetSymbolAddress((void**)&xn,    g_xn);
    cudaGetSymbolAddress((void**)&tr1,   g_trend1);
    cudaGetSymbolAddress((void**)&dst,   g_dstack);
    cudaGetSymbolAddress((void**)&h,     g_h);
    cudaGetSymbolAddress((void**)&o8,    g_out8);
    cudaGetSymbolAddress((void**)&o4,    g_out4);
    cudaGetSymbolAddress((void**)&o2,    g_out2);
    cudaGetSymbolAddress((void**)&means, g_means);
    cudaGetSymbolAddress((void**)&w1h,   g_w1h);
    cudaGetSymbolAddress((void**)&w2h,   g_w2h);

    __half* w1h8 = w1h;
    __half* w1h4 = w1h + 1024 * 128;
    __half* w1h2 = w1h + 1024 * (128 + 256);
    __half* w2h8 = w2h;
    __half* w2h4 = w2h + 1024 * 1024;
    __half* w2h2 = w2h + 2 * 1024 * 1024;

    cudaFuncSetAttribute(gemm_h_kernel,
                         cudaFuncAttributeMaxDynamicSharedMemorySize, GEMM_SMEM_B);

    /* launch 0: convert weights + zero mean-sums */
    prep_kernel<<<(NW_TOTAL + 255) / 256, 256>>>(w1_8, w1_4, w1_2, w2_8, w2_4, w2_2);
    /* launch 1 */
    bn_kernel<<<FEAT / 256, 256>>>(x, bng, bnb);
    /* launch 2: s=1 EMA + fused xn/trend1 row sums */
    ema_kernel<float, float><<<ROWS / 8, 256>>>(xn, tr1, al1, LEN,
                                                means + 3 * 2 * ROWS,
                                                means + 3 * 2 * ROWS + ROWS);

    /* s = 8 (launches 3,4,5,6 — launch 5 is GEMM1, ncu-captured) */
    {
        const int Ls = 128;
        dwconv_kernel<<<(ROWS * Ls + 255) / 256, 256>>>(xn, cw8, dst, 8, Ls);
        ema_kernel<__half, __half><<<ROWS / 8, 256>>>(dst, dst + (size_t)ROWS * Ls, al8, Ls, 0, 0);
        gemm_h_kernel<<<dim3(8, 128), 256, GEMM_SMEM_B>>>(dst, w1h8, h, b1_8, Ls, 1, 0);
        gemm_h_kernel<<<dim3(8, 128), 256, GEMM_SMEM_B>>>(h, w2h8, o8, b2_8, 1024, 0,
                                                          means + 0 * 2 * ROWS);
    }
    /* s = 4 */
    {
        const int Ls = 256;
        dwconv_kernel<<<(ROWS * Ls + 255) / 256, 256>>>(xn, cw4, dst, 4, Ls);
        ema_kernel<__half, __half><<<ROWS / 8, 256>>>(dst, dst + (size_t)ROWS * Ls, al4, Ls, 0, 0);
        gemm_h_kernel<<<dim3(8, 128), 256, GEMM_SMEM_B>>>(dst, w1h4, h, b1_4, Ls, 1, 0);
        gemm_h_kernel<<<dim3(8, 128), 256, GEMM_SMEM_B>>>(h, w2h4, o4, b2_4, 1024, 0,
                                                          means + 1 * 2 * ROWS);
    }
    /* s = 2 */
    {
        const int Ls = 512;
        dwconv_kernel<<<(ROWS * Ls + 255) / 256, 256>>>(xn, cw2, dst, 2, Ls);
        ema_kernel<__half, __half><<<ROWS / 8, 256>>>(dst, dst + (size_t)ROWS * Ls, al2, Ls, 0, 0);
        gemm_h_kernel<<<dim3(8, 128), 256, GEMM_SMEM_B>>>(dst, w1h2, h, b1_2, Ls, 1, 0);
        gemm_h_kernel<<<dim3(8, 128), 256, GEMM_SMEM_B>>>(h, w2h2, o2, b2_2, 1024, 0,
                                                          means + 2 * 2 * ROWS);
    }

    gate_kernel<<<BATCH, 128>>>(gw8, gb8, gw4, gb4, gw2, gb2, gw1, gb1);

    combine_kernel<<<(NELEM + 255) / 256, 256>>>(out);
}

// round 8
// speedup vs baseline: 4.0491x; 1.0817x over previous
#include <cuda_runtime.h>
#include <cuda_fp16.h>
#include <math.h>
#include <stdint.h>

#define BATCH 64
#define CH    128
#define LEN   1024
#define ROWS  (BATCH*CH)          /* 8192  */
#define FEAT  (CH*LEN)            /* 131072 */
#define NELEM (BATCH*CH*LEN)      /* 8388608 */

/* ---------------- scratch (static device globals; allocation-free) -------- */
__device__ float  g_xn[NELEM];
__device__ __half g_trend1[NELEM];
__device__ __half g_d8[2 * ROWS * 128];
__device__ __half g_d4[2 * ROWS * 256];
__device__ __half g_d2[2 * ROWS * 512];
__device__ __half g_h8[2 * ROWS * LEN];
__device__ __half g_h4[2 * ROWS * LEN];
__device__ __half g_h2[2 * ROWS * LEN];
__device__ __half g_o8[2 * ROWS * LEN];        /* [up ; trend], half          */
__device__ __half g_o4[2 * ROWS * LEN];
__device__ __half g_o2[2 * ROWS * LEN];
__device__ float  g_means[4 * 2 * ROWS];       /* row SUMS (÷L in gate)       */
__device__ float  g_gates[BATCH * 4];
__device__ __half g_w1h[1024 * (512 + 256 + 128)];
__device__ __half g_w2h[3 * 1024 * 1024];

/* ---------------- prep: convert all weights to half + zero mean-sums ------- */
#define NW_TOTAL (1024*(512+256+128) + 3*1024*1024)   /* 4063232 */
__global__ void prep_kernel(const float* __restrict__ w18, const float* __restrict__ w14,
                            const float* __restrict__ w12, const float* __restrict__ w28,
                            const float* __restrict__ w24, const float* __restrict__ w22) {
    int i = blockIdx.x * blockDim.x + threadIdx.x;
    if (i < 6 * ROWS) g_means[i] = 0.f;
    if (i >= NW_TOTAL) return;
    float v;
    int j = i;
    __half* dst;
    if (j < 131072)            { v = w18[j];            dst = g_w1h + j; }
    else if (j < 393216)       { v = w14[j - 131072];   dst = g_w1h + j; }
    else if (j < 917504)       { v = w12[j - 393216];   dst = g_w1h + j; }
    else if (j < 1966080)      { v = w28[j - 917504];   dst = g_w2h + (j - 917504); }
    else if (j < 3014656)      { v = w24[j - 1966080];  dst = g_w2h + (j - 917504); }
    else                       { v = w22[j - 3014656];  dst = g_w2h + (j - 917504); }
    *dst = __float2half_rn(v);
}

/* ---------------- BatchNorm over batch axis ------------------------------- */
__global__ void bn_kernel(const float* __restrict__ x,
                          const float* __restrict__ gam,
                          const float* __restrict__ bet) {
    int f = blockIdx.x * blockDim.x + threadIdx.x;
    if (f >= FEAT) return;
    float v[BATCH];
    float s = 0.f;
#pragma unroll
    for (int b = 0; b < BATCH; b++) { v[b] = x[(size_t)b * FEAT + f]; s += v[b]; }
    float mu = s * (1.f / BATCH);
    float q = 0.f;
#pragma unroll
    for (int b = 0; b < BATCH; b++) { float d = v[b] - mu; q += d * d; }
    float inv = rsqrtf(q * (1.f / BATCH) + 1e-5f);
    float gg = gam[f] * inv, bb = bet[f];
#pragma unroll
    for (int b = 0; b < BATCH; b++)
        g_xn[(size_t)b * FEAT + f] = (v[b] - mu) * gg + bb;
}

/* ---------------- depthwise strided conv (half output) -------------------- */
__global__ void dwconv_kernel(const float* __restrict__ xn,
                              const float* __restrict__ cw,
                              __half* __restrict__ out, int s, int Ls) {
    int idx = blockIdx.x * blockDim.x + threadIdx.x;
    if (idx >= ROWS * Ls) return;
    int t = idx % Ls, row = idx / Ls, c = row % CH;
    const float* xr = xn + (size_t)row * LEN;
    const float* w  = cw + c * 2 * s;
    int base = t * s - s / 2;
    float acc = 0.f;
    for (int k = 0; k < 2 * s; k++) {
        int p = base + k;
        if (p >= 0 && p < LEN) acc = fmaf(xr[p], w[k], acc);
    }
    out[idx] = __float2half_rn(acc);
}

/* ---------------- EMA (reference cumsum formulation), typed IO ------------- */
template <typename TI, typename TO>
__global__ void ema_kernel(const TI* __restrict__ src,
                           TO* __restrict__ dst,
                           const float* __restrict__ al, int Ls,
                           float* __restrict__ sumx, float* __restrict__ sumy) {
    int warp = (blockIdx.x * blockDim.x + threadIdx.x) >> 5;
    int lane = threadIdx.x & 31;
    if (warp >= ROWS) return;
    int c = warp % CH;
    float a  = 1.f / (1.f + expf(-al[c]));
    float om = 1.f - a;
    float l2 = log2f(om);
    const TI* x = src + (size_t)warp * Ls;
    TO* y       = dst + (size_t)warp * Ls;
    float cnum = 0.f, cden = 0.f;
    float sx = 0.f, sy = 0.f;
    for (int j0 = 0; j0 < Ls; j0 += 32) {
        int j = j0 + lane;
        float p = (float)(Ls - 1 - j);
        float base = exp2f(p * l2);
        float wn = (j == 0) ? base : base * a;
        float xv = (float)x[j];
        float n = xv * wn;
        float d = base;
#pragma unroll
        for (int o = 1; o < 32; o <<= 1) {
            float nn = __shfl_up_sync(0xffffffffu, n, o);
            float dd = __shfl_up_sync(0xffffffffu, d, o);
            if (lane >= o) { n += nn; d += dd; }
        }
        n += cnum; d += cden;
        float yv = n / fmaxf(d, 1e-12f);
        y[j] = (TO)yv;
        sx += xv; sy += yv;
        cnum = __shfl_sync(0xffffffffu, n, 31);
        cden = __shfl_sync(0xffffffffu, d, 31);
    }
    if (sumx) {
#pragma unroll
        for (int o = 16; o > 0; o >>= 1) {
            sx += __shfl_xor_sync(0xffffffffu, sx, o);
            sy += __shfl_xor_sync(0xffffffffu, sy, o);
        }
        if (lane == 0) { sumx[warp] = sx; sumy[warp] = sy; }
    }
}

/* ============ fp16 tensor-core GEMM  C[M,1024] = A[M,K]*B[N,K]^T =========== */
#define PITCH_H 72
#define PITCH_B 144
#define BKH 64
#define MAT_STAGE_B 18432
#define B_OFF 36864
#define GEMM_SMEM_B 73728

__device__ __forceinline__ uint32_t smem_u32(const void* p) {
    uint32_t a;
    asm("{.reg .u64 t; cvta.to.shared.u64 t, %1; cvt.u32.u64 %0, t;}"
        : "=r"(a) : "l"(p));
    return a;
}
__device__ __forceinline__ void cp_async16(uint32_t saddr, const void* g) {
    asm volatile("cp.async.cg.shared.global [%0], [%1], 16;"
                 :: "r"(saddr), "l"(g));
}
#define LDSM4(r0, r1, r2, r3, addr) \
    asm volatile("ldmatrix.sync.aligned.m8n8.x4.shared.b16 {%0,%1,%2,%3}, [%4];" \
                 : "=r"(r0), "=r"(r1), "=r"(r2), "=r"(r3) : "r"(addr))

__device__ __forceinline__ void mma_f16(float* d,
                                        const uint32_t* a, const uint32_t* b,
                                        const float* c) {
    asm volatile(
        "mma.sync.aligned.m16n8k16.row.col.f32.f16.f16.f32 "
        "{%0,%1,%2,%3}, {%4,%5,%6,%7}, {%8,%9}, {%10,%11,%12,%13};"
        : "=f"(d[0]), "=f"(d[1]), "=f"(d[2]), "=f"(d[3])
        : "r"(a[0]), "r"(a[1]), "r"(a[2]), "r"(a[3]),
          "r"(b[0]), "r"(b[1]),
          "f"(c[0]), "f"(c[1]), "f"(c[2]), "f"(c[3]));
}

__device__ __forceinline__ float gelu_exact(float v) {
    return 0.5f * v * (1.f + erff(v * 0.70710678118654752f));
}

/* act=1: gelu -> half (feeds GEMM2).  act=0: half u/t store + fp32 row sums. */
__global__ void __launch_bounds__(256, 2)
gemm_h_kernel(const __half* __restrict__ A, const __half* __restrict__ B,
              __half* __restrict__ Cout, const float* __restrict__ bias,
              int K, int act, float* __restrict__ sums) {
    extern __shared__ char smem[];
    const uint32_t sb = smem_u32(smem);
    const int tid  = threadIdx.x;
    const int wid  = tid >> 5;
    const int lane = tid & 31;
    const int g    = lane >> 2;
    const int tg   = lane & 3;
    const int wm   = (wid >> 1) * 32;
    const int wn   = (wid & 1) * 64;
    const int m0 = blockIdx.y * 128, n0 = blockIdx.x * 128;

    const int mat = tid >> 7, row = tid & 127;
    const __half* src = mat ? (B + (size_t)(n0 + row) * K)
                            : (A + (size_t)(m0 + row) * K);
    const uint32_t sldbase = sb + mat * B_OFF + row * PITCH_B;

    const int lr16 = lane & 15;
    const int lhi  = (lane >> 4) << 3;
    const uint32_t a_ab = sb + ((wm + lr16) * PITCH_H + lhi) * 2;
    const uint32_t b_ab = sb + B_OFF + ((wn + lr16) * PITCH_H + lhi) * 2;

    float acc[2][8][4];
#pragma unroll
    for (int i = 0; i < 2; i++)
#pragma unroll
        for (int j = 0; j < 8; j++)
#pragma unroll
            for (int q = 0; q < 4; q++) acc[i][j][q] = 0.f;

    const int niter = K / BKH;

#pragma unroll
    for (int c = 0; c < 8; c++)
        cp_async16(sldbase + c * 16, src + c * 8);
    asm volatile("cp.async.commit_group;");

    for (int i = 0; i < niter; i++) {
        if (i + 1 < niter) {
            const __half* gsrc = src + (i + 1) * BKH;
            uint32_t d = ((i + 1) & 1) * MAT_STAGE_B;
#pragma unroll
            for (int c = 0; c < 8; c++)
                cp_async16(sldbase + d + c * 16, gsrc + c * 8);
            asm volatile("cp.async.commit_group;");
            asm volatile("cp.async.wait_group 1;");
        } else {
            asm volatile("cp.async.wait_group 0;");
        }
        __syncthreads();

        const uint32_t stg = (i & 1) * MAT_STAGE_B;
        const uint32_t aa = a_ab + stg;
        const uint32_t bb = b_ab + stg;
#pragma unroll
        for (int kk = 0; kk < 4; kk++) {
            const uint32_t kb = kk * 32;
            uint32_t af[2][4], bf[8][2];
            LDSM4(af[0][0], af[0][1], af[0][2], af[0][3], aa + kb);
            LDSM4(af[1][0], af[1][1], af[1][2], af[1][3],
                  aa + kb + 16 * PITCH_B);
#pragma unroll
            for (int p = 0; p < 4; p++) {
                uint32_t q0, q1, q2, q3;
                LDSM4(q0, q1, q2, q3, bb + kb + p * 16 * PITCH_B);
                bf[2 * p][0] = q0; bf[2 * p + 1][0] = q1;
                bf[2 * p][1] = q2; bf[2 * p + 1][1] = q3;
            }
#pragma unroll
            for (int mt = 0; mt < 2; mt++)
#pragma unroll
                for (int nt = 0; nt < 8; nt++)
                    mma_f16(acc[mt][nt], af[mt], bf[nt], acc[mt][nt]);
        }
        __syncthreads();
    }

#pragma unroll
    for (int mt = 0; mt < 2; mt++) {
        int r0 = m0 + wm + mt * 16 + g;
        float s0 = 0.f, s1 = 0.f;
#pragma unroll
        for (int nt = 0; nt < 8; nt++) {
            int c0 = n0 + wn + nt * 8 + 2 * tg;
            float b0 = bias[c0], b1 = bias[c0 + 1];
            float v0 = acc[mt][nt][0] + b0;
            float v1 = acc[mt][nt][1] + b1;
            float v2 = acc[mt][nt][2] + b0;
            float v3 = acc[mt][nt][3] + b1;
            if (act) {
                v0 = gelu_exact(v0); v1 = gelu_exact(v1);
                v2 = gelu_exact(v2); v3 = gelu_exact(v3);
            } else {
                s0 += v0 + v1;
                s1 += v2 + v3;
            }
            *(__half2*)(Cout + (size_t)r0 * 1024 + c0)       = __floats2half2_rn(v0, v1);
            *(__half2*)(Cout + (size_t)(r0 + 8) * 1024 + c0) = __floats2half2_rn(v2, v3);
        }
        if (sums) {
            s0 += __shfl_xor_sync(0xffffffffu, s0, 1);
            s0 += __shfl_xor_sync(0xffffffffu, s0, 2);
            s1 += __shfl_xor_sync(0xffffffffu, s1, 1);
            s1 += __shfl_xor_sync(0xffffffffu, s1, 2);
            if (tg == 0) {
                atomicAdd(&sums[r0], s0);
                atomicAdd(&sums[r0 + 8], s1);
            }
        }
    }
}

/* ---------------- gates (means = sums / L) ---------------------------------- */
__global__ void gate_kernel(const float* __restrict__ gw8, const float* __restrict__ gb8,
                            const float* __restrict__ gw4, const float* __restrict__ gb4,
                            const float* __restrict__ gw2, const float* __restrict__ gb2,
                            const float* __restrict__ gw1, const float* __restrict__ gb1) {
    int b = blockIdx.x;
    int c = threadIdx.x;
    __shared__ float red[4][128];
    const float* gws[4] = {gw8, gw4, gw2, gw1};
    const float invL = 1.f / LEN;
    for (int s = 0; s < 4; s++) {
        float su = g_means[(s * 2 + 0) * ROWS + b * CH + c];
        float st = g_means[(s * 2 + 1) * ROWS + b * CH + c];
        red[s][c] = (su - st) * invL * gws[s][c];
    }
    __syncthreads();
    for (int o = 64; o > 0; o >>= 1) {
        if (c < o) {
            for (int s = 0; s < 4; s++) red[s][c] += red[s][c + o];
        }
        __syncthreads();
    }
    if (c == 0) {
        float gbv[4] = {gb8[0], gb4[0], gb2[0], gb1[0]};
        float gv[4], tot = 0.f;
        for (int s = 0; s < 4; s++) {
            gv[s] = 1.f / (1.f + expf(-(red[s][0] + gbv[s])));
            tot += gv[s];
        }
        for (int s = 0; s < 4; s++) g_gates[b * 4 + s] = gv[s] / (tot + 1e-6f);
    }
}

/* ---------------- final weighted combine; out = [season ; trend] ----------- */
__global__ void combine_kernel(float* __restrict__ out) {
    size_t idx = blockIdx.x * (size_t)blockDim.x + threadIdx.x;
    if (idx >= NELEM) return;
    int b = (int)(idx >> 10) / CH;
    const float* G = g_gates + b * 4;
    float g0 = G[0], g1 = G[1], g2 = G[2], g3 = G[3];
    float u8 = (float)g_o8[idx], t8 = (float)g_o8[idx + (size_t)NELEM];
    float u4 = (float)g_o4[idx], t4 = (float)g_o4[idx + (size_t)NELEM];
    float u2 = (float)g_o2[idx], t2 = (float)g_o2[idx + (size_t)NELEM];
    float u1 = g_xn[idx],        t1 = (float)g_trend1[idx];
    float trend  = g0 * t8 + g1 * t4 + g2 * t2 + g3 * t1;
    float season = g0 * (u8 - t8) + g1 * (u4 - t4) + g2 * (u2 - t2) + g3 * (u1 - t1);
    out[idx] = season;
    out[(size_t)NELEM + idx] = trend;
}

/* ---------------- host orchestration -------------------------------------- */
extern "C" void kernel_launch(void* const* d_in, const int* in_sizes, int n_in,
                              void* d_out, int out_size) {
    const float* x    = (const float*)d_in[0];
    const float* bng  = (const float*)d_in[1];
    const float* bnb  = (const float*)d_in[2];
    const float* cw8  = (const float*)d_in[3];
    const float* w1_8 = (const float*)d_in[4];
    const float* b1_8 = (const float*)d_in[5];
    const float* w2_8 = (const float*)d_in[6];
    const float* b2_8 = (const float*)d_in[7];
    const float* cw4  = (const float*)d_in[8];
    const float* w1_4 = (const float*)d_in[9];
    const float* b1_4 = (const float*)d_in[10];
    const float* w2_4 = (const float*)d_in[11];
    const float* b2_4 = (const float*)d_in[12];
    const float* cw2  = (const float*)d_in[13];
    const float* w1_2 = (const float*)d_in[14];
    const float* b1_2 = (const float*)d_in[15];
    const float* w2_2 = (const float*)d_in[16];
    const float* b2_2 = (const float*)d_in[17];
    const float* gw8  = (const float*)d_in[18];
    const float* gb8  = (const float*)d_in[19];
    const float* al8  = (const float*)d_in[20];
    const float* gw4  = (const float*)d_in[21];
    const float* gb4  = (const float*)d_in[22];
    const float* al4  = (const float*)d_in[23];
    const float* gw2  = (const float*)d_in[24];
    const float* gb2  = (const float*)d_in[25];
    const float* al2  = (const float*)d_in[26];
    const float* gw1  = (const float*)d_in[27];
    const float* gb1  = (const float*)d_in[28];
    const float* al1  = (const float*)d_in[29];
    float* out = (float*)d_out;

    float *xn, *means;
    __half *tr1, *d8, *d4, *d2, *h8, *h4, *h2, *o8, *o4, *o2, *w1h, *w2h;
    cudaGetSymbolAddress((void**)&xn,    g_xn);
    cudaGetSymbolAddress((void**)&tr1,   g_trend1);
    cudaGetSymbolAddress((void**)&d8,    g_d8);
    cudaGetSymbolAddress((void**)&d4,    g_d4);
    cudaGetSymbolAddress((void**)&d2,    g_d2);
    cudaGetSymbolAddress((void**)&h8,    g_h8);
    cudaGetSymbolAddress((void**)&h4,    g_h4);
    cudaGetSymbolAddress((void**)&h2,    g_h2);
    cudaGetSymbolAddress((void**)&o8,    g_o8);
    cudaGetSymbolAddress((void**)&o4,    g_o4);
    cudaGetSymbolAddress((void**)&o2,    g_o2);
    cudaGetSymbolAddress((void**)&means, g_means);
    cudaGetSymbolAddress((void**)&w1h,   g_w1h);
    cudaGetSymbolAddress((void**)&w2h,   g_w2h);

    __half* w1h8 = w1h;
    __half* w1h4 = w1h + 1024 * 128;
    __half* w1h2 = w1h + 1024 * (128 + 256);
    __half* w2h8 = w2h;
    __half* w2h4 = w2h + 1024 * 1024;
    __half* w2h2 = w2h + 2 * 1024 * 1024;

    cudaFuncSetAttribute(gemm_h_kernel,
                         cudaFuncAttributeMaxDynamicSharedMemorySize, GEMM_SMEM_B);

    /* streams/events created once (host-side objects, not device memory) */
    static cudaStream_t st[3];
    static cudaEvent_t  ev0, evb[3];
    static int sinit = 0;
    if (!sinit) {
        for (int i = 0; i < 3; i++)
            cudaStreamCreateWithFlags(&st[i], cudaStreamNonBlocking);
        cudaEventCreateWithFlags(&ev0, cudaEventDisableTiming);
        for (int i = 0; i < 3; i++)
            cudaEventCreateWithFlags(&evb[i], cudaEventDisableTiming);
        sinit = 1;
    }

    prep_kernel<<<(NW_TOTAL + 255) / 256, 256>>>(w1_8, w1_4, w1_2, w2_8, w2_4, w2_2);
    bn_kernel<<<FEAT / 256, 256>>>(x, bng, bnb);
    cudaEventRecord(ev0, 0);

    /* s=1 branch stays on the main stream */
    ema_kernel<float, __half><<<ROWS / 8, 256>>>(xn, tr1, al1, LEN,
                                                 means + 3 * 2 * ROWS,
                                                 means + 3 * 2 * ROWS + ROWS);

    /* s = 8 on st[0] */
    cudaStreamWaitEvent(st[0], ev0, 0);
    {
        const int Ls = 128;
        dwconv_kernel<<<(ROWS * Ls + 255) / 256, 256, 0, st[0]>>>(xn, cw8, d8, 8, Ls);
        ema_kernel<__half, __half><<<ROWS / 8, 256, 0, st[0]>>>(d8, d8 + (size_t)ROWS * Ls, al8, Ls, 0, 0);
        gemm_h_kernel<<<dim3(8, 128), 256, GEMM_SMEM_B, st[0]>>>(d8, w1h8, h8, b1_8, Ls, 1, 0);
        gemm_h_kernel<<<dim3(8, 128), 256, GEMM_SMEM_B, st[0]>>>(h8, w2h8, o8, b2_8, 1024, 0,
                                                                 means + 0 * 2 * ROWS);
    }
    cudaEventRecord(evb[0], st[0]);

    /* s = 4 on st[1] */
    cudaStreamWaitEvent(st[1], ev0, 0);
    {
        const int Ls = 256;
        dwconv_kernel<<<(ROWS * Ls + 255) / 256, 256, 0, st[1]>>>(xn, cw4, d4, 4, Ls);
        ema_kernel<__half, __half><<<ROWS / 8, 256, 0, st[1]>>>(d4, d4 + (size_t)ROWS * Ls, al4, Ls, 0, 0);
        gemm_h_kernel<<<dim3(8, 128), 256, GEMM_SMEM_B, st[1]>>>(d4, w1h4, h4, b1_4, Ls, 1, 0);
        gemm_h_kernel<<<dim3(8, 128), 256, GEMM_SMEM_B, st[1]>>>(h4, w2h4, o4, b2_4, 1024, 0,
                                                                 means + 1 * 2 * ROWS);
    }
    cudaEventRecord(evb[1], st[1]);

    /* s = 2 on st[2] */
    cudaStreamWaitEvent(st[2], ev0, 0);
    {
        const int Ls = 512;
        dwconv_kernel<<<(ROWS * Ls + 255) / 256, 256, 0, st[2]>>>(xn, cw2, d2, 2, Ls);
        ema_kernel<__half, __half><<<ROWS / 8, 256, 0, st[2]>>>(d2, d2 + (size_t)ROWS * Ls, al2, Ls, 0, 0);
        gemm_h_kernel<<<dim3(8, 128), 256, GEMM_SMEM_B, st[2]>>>(d2, w1h2, h2, b1_2, Ls, 1, 0);
        gemm_h_kernel<<<dim3(8, 128), 256, GEMM_SMEM_B, st[2]>>>(h2, w2h2, o2, b2_2, 1024, 0,
                                                                 means + 2 * 2 * ROWS);
    }
    cudaEventRecord(evb[2], st[2]);

    /* join */
    for (int i = 0; i < 3; i++)
        cudaStreamWaitEvent(0, evb[i], 0);

    gate_kernel<<<BATCH, 128>>>(gw8, gb8, gw4, gb4, gw2, gb2, gw1, gb1);
    combine_kernel<<<(NELEM + 255) / 256, 256>>>(out);
}